// round 2
// baseline (speedup 1.0000x reference)
#include <cuda_runtime.h>
#include <math.h>

// ---------------------------------------------------------------------------
// MechanismTransformerBlock  B=8 S=1024 D=1024 H=16 DH=64 DFF=4096
// fp32 tiled SGEMM (128x128x8, 8x8/thread, double-buffered smem)
// + fp32 flash attention with mechanism key-weighting.
// ---------------------------------------------------------------------------

namespace {
constexpr int Bc = 8, Sc = 1024, Dc = 1024, Hc = 16, DFFc = 4096;
constexpr int BS = Bc * Sc;                       // 8192 rows
constexpr size_t NXD = (size_t)BS * Dc;           // 8,388,608

constexpr size_t OFF_X    = 0;
constexpr size_t OFF_H    = OFF_X   + NXD;
constexpr size_t OFF_Q    = OFF_H   + NXD;
constexpr size_t OFF_K    = OFF_Q   + NXD;
constexpr size_t OFF_V    = OFF_K   + NXD;
constexpr size_t OFF_CTX  = OFF_V   + NXD;
constexpr size_t OFF_MH   = OFF_CTX + NXD;                    // BS x 512
constexpr size_t OFF_MECH = OFF_MH  + (size_t)BS * 512;       // BS
constexpr size_t OFF_PE   = OFF_MECH+ (size_t)BS;             // S x D
constexpr size_t OFF_PEP  = OFF_PE  + (size_t)Sc * Dc;        // S x D
constexpr size_t OFF_W5   = OFF_PEP + (size_t)Sc * Dc;        // D x D
constexpr size_t OFF_B5   = OFF_W5  + (size_t)Dc * Dc;        // D
constexpr size_t OFF_WSM  = OFF_B5  + Dc;                     // 8
constexpr size_t OFF_FFH  = OFF_WSM + 8;                      // BS x DFF
constexpr size_t TOTALF   = OFF_FFH + (size_t)BS * DFFc;
}

__device__ float g_buf[TOTALF];

__device__ __forceinline__ float gelu_exact(float v) {
    return 0.5f * v * (1.0f + erff(v * 0.70710678118654752440f));
}

// ---------------------------------------------------------------------------
// SGEMM: C[M,N] = act(A[M,K] @ B[K,N] + bias) + resid   (row-major, all dims
// multiples of tile sizes). 128x128 block tile, BK=8, 8x8 per thread.
// Double-buffered shared memory: one __syncthreads per K-slice; next tile's
// global loads issued before the FMA burst so they land under compute.
// ---------------------------------------------------------------------------
__global__ void __launch_bounds__(256, 2)
sgemm_k(const float* __restrict__ A, const float* __restrict__ Bm,
        const float* __restrict__ bias, const float* __restrict__ resid,
        float* __restrict__ C, int M, int N, int K, int act)
{
    __shared__ float As[2][8][128];
    __shared__ float Bs[2][8][128];
    const int tid = threadIdx.x;
    const int tx = tid & 15, ty = tid >> 4;
    const int bn = blockIdx.x, bm = blockIdx.y;
    const float* Ab = A + (size_t)bm * 128 * K;
    const float* Bb = Bm + (size_t)bn * 128;

    float acc[8][8];
#pragma unroll
    for (int i = 0; i < 8; i++)
#pragma unroll
        for (int j = 0; j < 8; j++) acc[i][j] = 0.f;

    const int arow = tid >> 1;            // 0..127
    const int acol = (tid & 1) * 4;       // 0 or 4
    const int brow = tid >> 5;            // 0..7
    const int bcol = (tid & 31) * 4;      // 0..124

    // preload tile 0 into buffer 0
    {
        float4 av = *(const float4*)(Ab + (size_t)arow * K + acol);
        As[0][acol + 0][arow] = av.x;
        As[0][acol + 1][arow] = av.y;
        As[0][acol + 2][arow] = av.z;
        As[0][acol + 3][arow] = av.w;
        float4 bv = *(const float4*)(Bb + (size_t)brow * N + bcol);
        *(float4*)&Bs[0][brow][bcol] = bv;
    }
    __syncthreads();

    int cur = 0;
    for (int k0 = 0; k0 < K; k0 += 8) {
        int nxt = cur ^ 1;
        // issue next tile's loads first (they complete while we compute)
        if (k0 + 8 < K) {
            float4 av = *(const float4*)(Ab + (size_t)arow * K + (k0 + 8) + acol);
            float4 bv = *(const float4*)(Bb + (size_t)(k0 + 8 + brow) * N + bcol);
            As[nxt][acol + 0][arow] = av.x;
            As[nxt][acol + 1][arow] = av.y;
            As[nxt][acol + 2][arow] = av.z;
            As[nxt][acol + 3][arow] = av.w;
            *(float4*)&Bs[nxt][brow][bcol] = bv;
        }
#pragma unroll
        for (int k = 0; k < 8; k++) {
            float4 a0 = *(const float4*)&As[cur][k][ty * 8];
            float4 a1 = *(const float4*)&As[cur][k][ty * 8 + 4];
            float4 b0 = *(const float4*)&Bs[cur][k][tx * 8];
            float4 b1 = *(const float4*)&Bs[cur][k][tx * 8 + 4];
            float ar[8] = {a0.x, a0.y, a0.z, a0.w, a1.x, a1.y, a1.z, a1.w};
            float br[8] = {b0.x, b0.y, b0.z, b0.w, b1.x, b1.y, b1.z, b1.w};
#pragma unroll
            for (int i = 0; i < 8; i++)
#pragma unroll
                for (int j = 0; j < 8; j++)
                    acc[i][j] = fmaf(ar[i], br[j], acc[i][j]);
        }
        __syncthreads();
        cur = nxt;
    }

#pragma unroll
    for (int i = 0; i < 8; i++) {
        int row = bm * 128 + ty * 8 + i;
        size_t ro = (size_t)row * N;
#pragma unroll
        for (int j = 0; j < 8; j++) {
            int col = bn * 128 + tx * 8 + j;
            float v = acc[i][j];
            if (bias) v += bias[col];
            if (act == 1) v = gelu_exact(v);
            if (resid) v += resid[ro + col];
            C[ro + col] = v;
        }
    }
}

// ---------------------------------------------------------------------------
// LayerNorm over last dim (1024). One block (256 threads) per row.
// ---------------------------------------------------------------------------
__global__ void layernorm_k(const float* __restrict__ x, const float* __restrict__ g,
                            const float* __restrict__ b, float* __restrict__ o)
{
    int row = blockIdx.x;
    const float4* xr = (const float4*)(x + (size_t)row * 1024);
    float4 v = xr[threadIdx.x];
    float s  = v.x + v.y + v.z + v.w;
    float ss = fmaf(v.x, v.x, fmaf(v.y, v.y, fmaf(v.z, v.z, v.w * v.w)));
#pragma unroll
    for (int off = 16; off > 0; off >>= 1) {
        s  += __shfl_xor_sync(0xffffffffu, s,  off);
        ss += __shfl_xor_sync(0xffffffffu, ss, off);
    }
    __shared__ float ws[8], wss[8];
    __shared__ float s_mean, s_inv;
    int w = threadIdx.x >> 5, ln = threadIdx.x & 31;
    if (ln == 0) { ws[w] = s; wss[w] = ss; }
    __syncthreads();
    if (threadIdx.x == 0) {
        float S = 0.f, SS = 0.f;
#pragma unroll
        for (int i = 0; i < 8; i++) { S += ws[i]; SS += wss[i]; }
        float mean = S * (1.f / 1024.f);
        float var  = SS * (1.f / 1024.f) - mean * mean;
        s_mean = mean;
        s_inv  = rsqrtf(var + 1e-5f);
    }
    __syncthreads();
    float mean = s_mean, inv = s_inv;
    float4 gv = ((const float4*)g)[threadIdx.x];
    float4 bv = ((const float4*)b)[threadIdx.x];
    float4 r;
    r.x = (v.x - mean) * inv * gv.x + bv.x;
    r.y = (v.y - mean) * inv * gv.y + bv.y;
    r.z = (v.z - mean) * inv * gv.z + bv.z;
    r.w = (v.w - mean) * inv * gv.w + bv.w;
    ((float4*)(o + (size_t)row * 1024))[threadIdx.x] = r;
}

// ---------------------------------------------------------------------------
// Small elementwise kernels
// ---------------------------------------------------------------------------
__global__ void build_pe_k(const float* __restrict__ pos, const float* __restrict__ tim,
                           float* __restrict__ pe)
{
    int i = blockIdx.x * blockDim.x + threadIdx.x;   // S*D = 1M
    int s = i >> 10, d = i & 1023;
    pe[i] = (d < 512) ? pos[s * 512 + d] : tim[s * 512 + (d - 512)];
}

__global__ void add_pe_k(const float* __restrict__ xin, const float* __restrict__ pep,
                         float* __restrict__ x)
{
    size_t i = (size_t)blockIdx.x * blockDim.x + threadIdx.x;  // B*S*D
    x[i] = xin[i] + pep[i & ((size_t)(1 << 20) - 1)];
}

__global__ void softmax5_k(const float* __restrict__ elw, float* __restrict__ wsm,
                           float* __restrict__ out_w)
{
    if (threadIdx.x == 0) {
        float m = elw[0];
        for (int p = 1; p < 5; p++) m = fmaxf(m, elw[p]);
        float e[5], s = 0.f;
        for (int p = 0; p < 5; p++) { e[p] = expf(elw[p] - m); s += e[p]; }
        float inv = 1.f / s;
        for (int p = 0; p < 5; p++) { wsm[p] = e[p] * inv; out_w[p] = e[p] * inv; }
    }
}

__global__ void combine_w5_k(const float* __restrict__ ew, const float* __restrict__ wsm,
                             float* __restrict__ w5)
{
    int i = blockIdx.x * blockDim.x + threadIdx.x;   // D*D
    float w0 = wsm[0], w1 = wsm[1], w2 = wsm[2], w3 = wsm[3], w4 = wsm[4];
    const size_t DD = (size_t)1024 * 1024;
    float v = w0 * ew[i] + w1 * ew[DD + i] + w2 * ew[2 * DD + i]
            + w3 * ew[3 * DD + i] + w4 * ew[4 * DD + i];
    w5[i] = v;
}

__global__ void combine_b5_k(const float* __restrict__ eb, const float* __restrict__ wsm,
                             float* __restrict__ b5)
{
    int i = blockIdx.x * blockDim.x + threadIdx.x;   // D
    float v = 0.f;
    for (int p = 0; p < 5; p++) v += wsm[p] * eb[p * 1024 + i];
    b5[i] = v;
}

// mech[r] = sigmoid(dot(mh[r,:512], mw2) + mb2); one warp per row.
__global__ void mech_out_k(const float* __restrict__ mh, const float* __restrict__ mw2,
                           const float* __restrict__ mb2, float* __restrict__ mech,
                           float* __restrict__ out_mech)
{
    int row  = blockIdx.x * 8 + (threadIdx.x >> 5);
    int lane = threadIdx.x & 31;
    const float* r = mh + (size_t)row * 512;
    float s = 0.f;
#pragma unroll
    for (int c = lane; c < 512; c += 32) s = fmaf(r[c], mw2[c], s);
#pragma unroll
    for (int off = 16; off > 0; off >>= 1) s += __shfl_xor_sync(0xffffffffu, s, off);
    if (lane == 0) {
        float t = s + mb2[0];
        float m = 1.f / (1.f + expf(-t));
        mech[row] = m;
        out_mech[row] = m;
    }
}

// ---------------------------------------------------------------------------
// Flash attention (fp32). Per block: one (b,h) and a 64-row Q tile.
// scores = (Q K^T / 8) * (1 + mech[key]); online softmax; ctx = P V.
// block = 256 threads as 16x16, each owning 4x4 fragments.
// ---------------------------------------------------------------------------
__global__ void __launch_bounds__(256, 2)
attn_k(const float* __restrict__ Q, const float* __restrict__ Kp,
       const float* __restrict__ Vp, const float* __restrict__ mech,
       float* __restrict__ Octx)
{
    extern __shared__ float sm[];
    const int PAD = 68;
    float* QsT  = sm;                 // [64][68] transposed (d major)
    float* KsT  = QsT + 64 * PAD;     // [64][68] transposed
    float* Vs   = KsT + 64 * PAD;     // [64][68]
    float* PsT  = Vs  + 64 * PAD;     // [64][68] (k major)
    float* red  = PsT + 64 * PAD;     // [64][16]
    float* red2 = red + 64 * 16;      // [64][16]
    float* m_i  = red2 + 64 * 16;     // [64]
    float* l_i  = m_i + 64;           // [64]
    float* alp  = l_i + 64;           // [64]
    float* fac  = alp + 64;           // [64]

    const int tid = threadIdx.x;
    const int tx = tid & 15, ty = tid >> 4;
    const int bh = blockIdx.y;
    const int b = bh >> 4, h = bh & 15;
    const int q0 = blockIdx.x * 64;
    const size_t base = (size_t)b * Sc * Dc + (size_t)h * 64;

    // Load Q tile (transposed into QsT[d][q])
    {
        int r = tid >> 2;
        int d0 = (tid & 3) * 16;
        const float* qp = Q + base + (size_t)(q0 + r) * Dc + d0;
#pragma unroll
        for (int u = 0; u < 4; u++) {
            float4 v = *(const float4*)(qp + u * 4);
            QsT[(d0 + u * 4 + 0) * PAD + r] = v.x;
            QsT[(d0 + u * 4 + 1) * PAD + r] = v.y;
            QsT[(d0 + u * 4 + 2) * PAD + r] = v.z;
            QsT[(d0 + u * 4 + 3) * PAD + r] = v.w;
        }
    }
    if (tid < 64) { m_i[tid] = -1e30f; l_i[tid] = 0.f; }
    float acc[4][4];
#pragma unroll
    for (int i = 0; i < 4; i++)
#pragma unroll
        for (int j = 0; j < 4; j++) acc[i][j] = 0.f;
    __syncthreads();

    for (int kt = 0; kt < 16; kt++) {
        const int k0 = kt * 64;
        // Load K (transposed), V (direct), mech factors
        {
            int r = tid >> 2;
            int d0 = (tid & 3) * 16;
            const float* kp = Kp + base + (size_t)(k0 + r) * Dc + d0;
            const float* vp = Vp + base + (size_t)(k0 + r) * Dc + d0;
#pragma unroll
            for (int u = 0; u < 4; u++) {
                float4 v = *(const float4*)(kp + u * 4);
                KsT[(d0 + u * 4 + 0) * PAD + r] = v.x;
                KsT[(d0 + u * 4 + 1) * PAD + r] = v.y;
                KsT[(d0 + u * 4 + 2) * PAD + r] = v.z;
                KsT[(d0 + u * 4 + 3) * PAD + r] = v.w;
                float4 w = *(const float4*)(vp + u * 4);
                *(float4*)&Vs[r * PAD + d0 + u * 4] = w;
            }
        }
        if (tid < 64) fac[tid] = 1.f + mech[(size_t)b * Sc + k0 + tid];
        __syncthreads();

        // S tile = Q K^T  (each thread 4x4)
        float s[4][4];
#pragma unroll
        for (int i = 0; i < 4; i++)
#pragma unroll
            for (int j = 0; j < 4; j++) s[i][j] = 0.f;
#pragma unroll 4
        for (int d = 0; d < 64; d++) {
            float4 qv = *(const float4*)&QsT[d * PAD + ty * 4];
            float4 kv = *(const float4*)&KsT[d * PAD + tx * 4];
            float qa[4] = {qv.x, qv.y, qv.z, qv.w};
            float ka[4] = {kv.x, kv.y, kv.z, kv.w};
#pragma unroll
            for (int i = 0; i < 4; i++)
#pragma unroll
                for (int j = 0; j < 4; j++)
                    s[i][j] = fmaf(qa[i], ka[j], s[i][j]);
        }
        float fj[4];
#pragma unroll
        for (int j = 0; j < 4; j++) fj[j] = 0.125f * fac[tx * 4 + j];
#pragma unroll
        for (int i = 0; i < 4; i++)
#pragma unroll
            for (int j = 0; j < 4; j++) s[i][j] *= fj[j];

        // partial row max
#pragma unroll
        for (int i = 0; i < 4; i++) {
            float pm = fmaxf(fmaxf(s[i][0], s[i][1]), fmaxf(s[i][2], s[i][3]));
            red[(ty * 4 + i) * 16 + tx] = pm;
        }
        __syncthreads();

        float mnew[4];
#pragma unroll
        for (int i = 0; i < 4; i++) {
            int r = ty * 4 + i;
            float m = m_i[r];
#pragma unroll
            for (int t = 0; t < 16; t++) m = fmaxf(m, red[r * 16 + t]);
            mnew[i] = m;
        }
        // p = exp(s - mnew), write P (transposed, k major) + partial sums
        float psum[4] = {0.f, 0.f, 0.f, 0.f};
#pragma unroll
        for (int i = 0; i < 4; i++) {
#pragma unroll
            for (int j = 0; j < 4; j++) {
                float p = expf(s[i][j] - mnew[i]);
                PsT[(tx * 4 + j) * PAD + ty * 4 + i] = p;
                psum[i] += p;
            }
            red2[(ty * 4 + i) * 16 + tx] = psum[i];
        }
        __syncthreads();

        if (tx == 0) {
#pragma unroll
            for (int i = 0; i < 4; i++) {
                int r = ty * 4 + i;
                float ls = 0.f;
#pragma unroll
                for (int t = 0; t < 16; t++) ls += red2[r * 16 + t];
                float a = expf(m_i[r] - mnew[i]);
                l_i[r] = l_i[r] * a + ls;
                m_i[r] = mnew[i];
                alp[r] = a;
            }
        }
        __syncthreads();

        float av[4];
#pragma unroll
        for (int i = 0; i < 4; i++) av[i] = alp[ty * 4 + i];
#pragma unroll
        for (int i = 0; i < 4; i++)
#pragma unroll
            for (int j = 0; j < 4; j++) acc[i][j] *= av[i];

        // acc += P V
#pragma unroll 4
        for (int k = 0; k < 64; k++) {
            float4 pv = *(const float4*)&PsT[k * PAD + ty * 4];
            float4 vv = *(const float4*)&Vs[k * PAD + tx * 4];
            float pa[4] = {pv.x, pv.y, pv.z, pv.w};
            float va[4] = {vv.x, vv.y, vv.z, vv.w};
#pragma unroll
            for (int i = 0; i < 4; i++)
#pragma unroll
                for (int j = 0; j < 4; j++)
                    acc[i][j] = fmaf(pa[i], va[j], acc[i][j]);
        }
        __syncthreads();
    }

    // epilogue: O = acc / l
#pragma unroll
    for (int i = 0; i < 4; i++) {
        int r = ty * 4 + i;
        float inv = 1.f / l_i[r];
        float4 o;
        o.x = acc[i][0] * inv;
        o.y = acc[i][1] * inv;
        o.z = acc[i][2] * inv;
        o.w = acc[i][3] * inv;
        *(float4*)&Octx[base + (size_t)(q0 + r) * Dc + tx * 4] = o;
    }
}

// ---------------------------------------------------------------------------
// Host launcher
// ---------------------------------------------------------------------------
extern "C" void kernel_launch(void* const* d_in, const int* in_sizes, int n_in,
                              void* d_out, int out_size)
{
    (void)in_sizes; (void)n_in; (void)out_size;
    const float* x_in = (const float*)d_in[0];
    const float* pos  = (const float*)d_in[1];
    const float* tim  = (const float*)d_in[2];
    const float* wi   = (const float*)d_in[3];
    const float* bi   = (const float*)d_in[4];
    const float* g1   = (const float*)d_in[5];
    const float* be1  = (const float*)d_in[6];
    const float* g2   = (const float*)d_in[7];
    const float* be2  = (const float*)d_in[8];
    const float* g3   = (const float*)d_in[9];
    const float* be3  = (const float*)d_in[10];
    const float* qw   = (const float*)d_in[11];
    const float* qb   = (const float*)d_in[12];
    const float* kw   = (const float*)d_in[13];
    const float* kb   = (const float*)d_in[14];
    const float* vw   = (const float*)d_in[15];
    const float* vb   = (const float*)d_in[16];
    const float* ow   = (const float*)d_in[17];
    const float* ob   = (const float*)d_in[18];
    const float* mw1  = (const float*)d_in[19];
    const float* mb1  = (const float*)d_in[20];
    const float* mw2  = (const float*)d_in[21];
    const float* mb2  = (const float*)d_in[22];
    const float* ew   = (const float*)d_in[23];
    const float* eb   = (const float*)d_in[24];
    const float* elw  = (const float*)d_in[25];
    const float* fw1  = (const float*)d_in[26];
    const float* fb1  = (const float*)d_in[27];
    const float* fw2  = (const float*)d_in[28];
    const float* fb2  = (const float*)d_in[29];

    float* out = (float*)d_out;
    float* out_mech = out + NXD;          // 8,388,608
    float* out_w    = out + NXD + BS;     // +8192

    float* base = nullptr;
    cudaGetSymbolAddress((void**)&base, g_buf);
    float* gx   = base + OFF_X;
    float* gh   = base + OFF_H;
    float* gq   = base + OFF_Q;
    float* gk   = base + OFF_K;
    float* gv   = base + OFF_V;
    float* gctx = base + OFF_CTX;
    float* gmh  = base + OFF_MH;
    float* gmech= base + OFF_MECH;
    float* gpe  = base + OFF_PE;
    float* gpep = base + OFF_PEP;
    float* gw5  = base + OFF_W5;
    float* gb5  = base + OFF_B5;
    float* gwsm = base + OFF_WSM;
    float* gffh = base + OFF_FFH;

    const int ATTN_SMEM = (4 * 64 * 68 + 2 * 64 * 16 + 4 * 64) * (int)sizeof(float);
    cudaFuncSetAttribute(attn_k, cudaFuncAttributeMaxDynamicSharedMemorySize, ATTN_SMEM);

    // 1) positional/timing embedding: pe = concat(pos, time); x = x_in + pe@wi + bi
    build_pe_k<<<(Sc * Dc) / 256, 256>>>(pos, tim, gpe);
    sgemm_k<<<dim3(Dc / 128, Sc / 128), 256>>>(gpe, wi, bi, nullptr, gpep, Sc, Dc, Dc, 0);
    add_pe_k<<<(unsigned)(NXD / 256), 256>>>(x_in, gpep, gx);

    // 2) norm1 -> h
    layernorm_k<<<BS, 256>>>(gx, g1, be1, gh);

    // 3) q,k,v projections
    sgemm_k<<<dim3(Dc / 128, BS / 128), 256>>>(gh, qw, qb, nullptr, gq, BS, Dc, Dc, 0);
    sgemm_k<<<dim3(Dc / 128, BS / 128), 256>>>(gh, kw, kb, nullptr, gk, BS, Dc, Dc, 0);
    sgemm_k<<<dim3(Dc / 128, BS / 128), 256>>>(gh, vw, vb, nullptr, gv, BS, Dc, Dc, 0);

    // 4) mechanism MLP: gelu(h@mw1+mb1) @ mw2 + mb2 -> sigmoid
    sgemm_k<<<dim3(512 / 128, BS / 128), 256>>>(gh, mw1, mb1, nullptr, gmh, BS, 512, Dc, 1);
    mech_out_k<<<BS / 8, 256>>>(gmh, mw2, mb2, gmech, out_mech);

    // 5) flash attention with mechanism key-weighting
    attn_k<<<dim3(Sc / 64, Bc * Hc), 256, ATTN_SMEM>>>(gq, gk, gv, gmech, gctx);

    // 6) output projection + residual
    sgemm_k<<<dim3(Dc / 128, BS / 128), 256>>>(gctx, ow, ob, gx, gx, BS, Dc, Dc, 0);

    // 7) five elements: fold 5 projections into one via softmax(elw) weights
    layernorm_k<<<BS, 256>>>(gx, g2, be2, gh);
    softmax5_k<<<1, 32>>>(elw, gwsm, out_w);
    combine_w5_k<<<(Dc * Dc) / 256, 256>>>(ew, gwsm, gw5);
    combine_b5_k<<<Dc / 256, 256>>>(eb, gwsm, gb5);
    sgemm_k<<<dim3(Dc / 128, BS / 128), 256>>>(gh, gw5, gb5, gx, gx, BS, Dc, Dc, 0);

    // 8) FFN
    layernorm_k<<<BS, 256>>>(gx, g3, be3, gh);
    sgemm_k<<<dim3(DFFc / 128, BS / 128), 256>>>(gh, fw1, fb1, nullptr, gffh, BS, DFFc, Dc, 1);
    // final: write x directly into d_out
    sgemm_k<<<dim3(Dc / 128, BS / 128), 256>>>(gffh, fw2, fb2, gx, out, BS, Dc, DFFc, 0);
}

// round 3
// speedup vs baseline: 2.0821x; 2.0821x over previous
#include <cuda_runtime.h>
#include <math.h>
#include <stdint.h>

// ---------------------------------------------------------------------------
// MechanismTransformerBlock  B=8 S=1024 D=1024 H=16 DH=64 DFF=4096
// TF32 tensor-core GEMM (mma.sync m16n8k8, 128x128x16 tiles, double-buffered)
// + fp32 flash attention with mechanism key-weighting.
// ---------------------------------------------------------------------------

namespace {
constexpr int Bc = 8, Sc = 1024, Dc = 1024, Hc = 16, DFFc = 4096;
constexpr int BS = Bc * Sc;                       // 8192 rows
constexpr size_t NXD = (size_t)BS * Dc;           // 8,388,608

constexpr size_t OFF_X    = 0;
constexpr size_t OFF_H    = OFF_X   + NXD;
constexpr size_t OFF_Q    = OFF_H   + NXD;
constexpr size_t OFF_K    = OFF_Q   + NXD;
constexpr size_t OFF_V    = OFF_K   + NXD;
constexpr size_t OFF_CTX  = OFF_V   + NXD;
constexpr size_t OFF_MH   = OFF_CTX + NXD;                    // BS x 512
constexpr size_t OFF_MECH = OFF_MH  + (size_t)BS * 512;       // BS
constexpr size_t OFF_PE   = OFF_MECH+ (size_t)BS;             // S x D
constexpr size_t OFF_PEP  = OFF_PE  + (size_t)Sc * Dc;        // S x D
constexpr size_t OFF_W5   = OFF_PEP + (size_t)Sc * Dc;        // D x D
constexpr size_t OFF_B5   = OFF_W5  + (size_t)Dc * Dc;        // D
constexpr size_t OFF_WSM  = OFF_B5  + Dc;                     // 8
constexpr size_t OFF_FFH  = OFF_WSM + 8;                      // BS x DFF
constexpr size_t TOTALF   = OFF_FFH + (size_t)BS * DFFc;
}

__device__ float g_buf[TOTALF];

__device__ __forceinline__ float gelu_exact(float v) {
    return 0.5f * v * (1.0f + erff(v * 0.70710678118654752440f));
}

__device__ __forceinline__ float f2tf32(float f) {
    uint32_t r;
    asm("cvt.rna.tf32.f32 %0, %1;" : "=r"(r) : "f"(f));
    return __uint_as_float(r);
}

__device__ __forceinline__ void mma_tf32(float* c, const uint32_t* a, const uint32_t* b) {
    asm volatile(
        "mma.sync.aligned.m16n8k8.row.col.f32.tf32.tf32.f32 "
        "{%0,%1,%2,%3}, {%4,%5,%6,%7}, {%8,%9}, {%0,%1,%2,%3};\n"
        : "+f"(c[0]), "+f"(c[1]), "+f"(c[2]), "+f"(c[3])
        : "r"(a[0]), "r"(a[1]), "r"(a[2]), "r"(a[3]), "r"(b[0]), "r"(b[1]));
}

// ---------------------------------------------------------------------------
// TF32 GEMM: C[M,N] = act(A[M,K] @ B[K,N] + bias) + resid   (row-major).
// 128x128 block tile, BK=16, 256 threads = 8 warps (4M x 2N), warp tile 32x64.
// A smem stored k-major [16][PITCH] (transposed), B smem [16][PITCH].
// PITCH=136 => fragment LDS bank = (8*(lane%4) + lane/4) mod 32, conflict-free.
// Inputs rounded to tf32 once at the smem-store stage; fp32 accumulation.
// ---------------------------------------------------------------------------
#define GP 136

__global__ void __launch_bounds__(256, 2)
tgemm_k(const float* __restrict__ A, const float* __restrict__ Bm,
        const float* __restrict__ bias, const float* __restrict__ resid,
        float* __restrict__ C, int M, int N, int K, int act)
{
    __shared__ float As[2][16][GP];
    __shared__ float Bs[2][16][GP];

    const int tid = threadIdx.x;
    const int w = tid >> 5, l = tid & 31;
    const int wm = (w & 3) * 32;          // warp M offset in block tile
    const int wn = (w >> 2) * 64;         // warp N offset in block tile
    const int g = l >> 2, t = l & 3;      // mma lane decomposition
    const int bn = blockIdx.x, bm = blockIdx.y;
    const float* Ab = A + (size_t)bm * 128 * K;
    const float* Bb = Bm + (size_t)bn * 128;

    const int arow = tid >> 1;            // 0..127
    const int acol = (tid & 1) * 8;       // 0 or 8
    const int brow = tid >> 4;            // 0..15
    const int bcol = (tid & 15) * 8;      // 0..120

    float acc[2][8][4];
#pragma unroll
    for (int i = 0; i < 2; i++)
#pragma unroll
        for (int j = 0; j < 8; j++)
#pragma unroll
            for (int r = 0; r < 4; r++) acc[i][j][r] = 0.f;

    // ---- prologue: load tile 0 into buffer 0 ----
    {
        const float* Ap = Ab + (size_t)arow * K + acol;
        float4 a0 = *(const float4*)Ap;
        float4 a1 = *(const float4*)(Ap + 4);
        As[0][acol + 0][arow] = f2tf32(a0.x);
        As[0][acol + 1][arow] = f2tf32(a0.y);
        As[0][acol + 2][arow] = f2tf32(a0.z);
        As[0][acol + 3][arow] = f2tf32(a0.w);
        As[0][acol + 4][arow] = f2tf32(a1.x);
        As[0][acol + 5][arow] = f2tf32(a1.y);
        As[0][acol + 6][arow] = f2tf32(a1.z);
        As[0][acol + 7][arow] = f2tf32(a1.w);
        const float* Bp = Bb + (size_t)brow * N + bcol;
        float4 b0 = *(const float4*)Bp;
        float4 b1 = *(const float4*)(Bp + 4);
        float4 c0 = make_float4(f2tf32(b0.x), f2tf32(b0.y), f2tf32(b0.z), f2tf32(b0.w));
        float4 c1 = make_float4(f2tf32(b1.x), f2tf32(b1.y), f2tf32(b1.z), f2tf32(b1.w));
        *(float4*)&Bs[0][brow][bcol]     = c0;
        *(float4*)&Bs[0][brow][bcol + 4] = c1;
    }
    __syncthreads();

    int cur = 0;
    for (int k0 = 0; k0 < K; k0 += 16) {
        const bool hn = (k0 + 16) < K;
        float4 na0, na1, nb0, nb1;
        if (hn) {
            const float* Ap = Ab + (size_t)arow * K + (k0 + 16) + acol;
            na0 = *(const float4*)Ap;
            na1 = *(const float4*)(Ap + 4);
            const float* Bp = Bb + (size_t)(k0 + 16 + brow) * N + bcol;
            nb0 = *(const float4*)Bp;
            nb1 = *(const float4*)(Bp + 4);
        }

#pragma unroll
        for (int ks = 0; ks < 2; ks++) {
            const int kb = ks * 8;
            uint32_t af[2][4], bf[8][2];
#pragma unroll
            for (int i = 0; i < 2; i++) {
                const float* p0 = &As[cur][kb + t][wm + i * 16 + g];
                const float* p1 = &As[cur][kb + t + 4][wm + i * 16 + g];
                af[i][0] = __float_as_uint(p0[0]);
                af[i][1] = __float_as_uint(p0[8]);
                af[i][2] = __float_as_uint(p1[0]);
                af[i][3] = __float_as_uint(p1[8]);
            }
#pragma unroll
            for (int j = 0; j < 8; j++) {
                bf[j][0] = __float_as_uint(Bs[cur][kb + t][wn + j * 8 + g]);
                bf[j][1] = __float_as_uint(Bs[cur][kb + t + 4][wn + j * 8 + g]);
            }
#pragma unroll
            for (int i = 0; i < 2; i++)
#pragma unroll
                for (int j = 0; j < 8; j++)
                    mma_tf32(acc[i][j], af[i], bf[j]);
        }

        if (hn) {
            int nxt = cur ^ 1;
            As[nxt][acol + 0][arow] = f2tf32(na0.x);
            As[nxt][acol + 1][arow] = f2tf32(na0.y);
            As[nxt][acol + 2][arow] = f2tf32(na0.z);
            As[nxt][acol + 3][arow] = f2tf32(na0.w);
            As[nxt][acol + 4][arow] = f2tf32(na1.x);
            As[nxt][acol + 5][arow] = f2tf32(na1.y);
            As[nxt][acol + 6][arow] = f2tf32(na1.z);
            As[nxt][acol + 7][arow] = f2tf32(na1.w);
            float4 c0 = make_float4(f2tf32(nb0.x), f2tf32(nb0.y), f2tf32(nb0.z), f2tf32(nb0.w));
            float4 c1 = make_float4(f2tf32(nb1.x), f2tf32(nb1.y), f2tf32(nb1.z), f2tf32(nb1.w));
            *(float4*)&Bs[nxt][brow][bcol]     = c0;
            *(float4*)&Bs[nxt][brow][bcol + 4] = c1;
        }
        __syncthreads();
        cur ^= 1;
    }

    // ---- epilogue ----
#pragma unroll
    for (int i = 0; i < 2; i++) {
        int row0 = bm * 128 + wm + i * 16 + g;
        int row1 = row0 + 8;
        size_t ro0 = (size_t)row0 * N;
        size_t ro1 = (size_t)row1 * N;
#pragma unroll
        for (int j = 0; j < 8; j++) {
            int col = bn * 128 + wn + j * 8 + 2 * t;
            float v0 = acc[i][j][0], v1 = acc[i][j][1];
            float v2 = acc[i][j][2], v3 = acc[i][j][3];
            if (bias) {
                float b0 = bias[col], b1 = bias[col + 1];
                v0 += b0; v1 += b1; v2 += b0; v3 += b1;
            }
            if (act == 1) {
                v0 = gelu_exact(v0); v1 = gelu_exact(v1);
                v2 = gelu_exact(v2); v3 = gelu_exact(v3);
            }
            if (resid) {
                v0 += resid[ro0 + col]; v1 += resid[ro0 + col + 1];
                v2 += resid[ro1 + col]; v3 += resid[ro1 + col + 1];
            }
            *(float2*)&C[ro0 + col] = make_float2(v0, v1);
            *(float2*)&C[ro1 + col] = make_float2(v2, v3);
        }
    }
}

// ---------------------------------------------------------------------------
// LayerNorm over last dim (1024). One block (256 threads) per row.
// ---------------------------------------------------------------------------
__global__ void layernorm_k(const float* __restrict__ x, const float* __restrict__ g,
                            const float* __restrict__ b, float* __restrict__ o)
{
    int row = blockIdx.x;
    const float4* xr = (const float4*)(x + (size_t)row * 1024);
    float4 v = xr[threadIdx.x];
    float s  = v.x + v.y + v.z + v.w;
    float ss = fmaf(v.x, v.x, fmaf(v.y, v.y, fmaf(v.z, v.z, v.w * v.w)));
#pragma unroll
    for (int off = 16; off > 0; off >>= 1) {
        s  += __shfl_xor_sync(0xffffffffu, s,  off);
        ss += __shfl_xor_sync(0xffffffffu, ss, off);
    }
    __shared__ float ws[8], wss[8];
    __shared__ float s_mean, s_inv;
    int w = threadIdx.x >> 5, ln = threadIdx.x & 31;
    if (ln == 0) { ws[w] = s; wss[w] = ss; }
    __syncthreads();
    if (threadIdx.x == 0) {
        float S = 0.f, SS = 0.f;
#pragma unroll
        for (int i = 0; i < 8; i++) { S += ws[i]; SS += wss[i]; }
        float mean = S * (1.f / 1024.f);
        float var  = SS * (1.f / 1024.f) - mean * mean;
        s_mean = mean;
        s_inv  = rsqrtf(var + 1e-5f);
    }
    __syncthreads();
    float mean = s_mean, inv = s_inv;
    float4 gv = ((const float4*)g)[threadIdx.x];
    float4 bv = ((const float4*)b)[threadIdx.x];
    float4 r;
    r.x = (v.x - mean) * inv * gv.x + bv.x;
    r.y = (v.y - mean) * inv * gv.y + bv.y;
    r.z = (v.z - mean) * inv * gv.z + bv.z;
    r.w = (v.w - mean) * inv * gv.w + bv.w;
    ((float4*)(o + (size_t)row * 1024))[threadIdx.x] = r;
}

// ---------------------------------------------------------------------------
// Small elementwise kernels
// ---------------------------------------------------------------------------
__global__ void build_pe_k(const float* __restrict__ pos, const float* __restrict__ tim,
                           float* __restrict__ pe)
{
    int i = blockIdx.x * blockDim.x + threadIdx.x;   // S*D = 1M
    int s = i >> 10, d = i & 1023;
    pe[i] = (d < 512) ? pos[s * 512 + d] : tim[s * 512 + (d - 512)];
}

__global__ void add_pe_k(const float* __restrict__ xin, const float* __restrict__ pep,
                         float* __restrict__ x)
{
    size_t i = (size_t)blockIdx.x * blockDim.x + threadIdx.x;  // B*S*D
    x[i] = xin[i] + pep[i & ((size_t)(1 << 20) - 1)];
}

__global__ void softmax5_k(const float* __restrict__ elw, float* __restrict__ wsm,
                           float* __restrict__ out_w)
{
    if (threadIdx.x == 0) {
        float m = elw[0];
        for (int p = 1; p < 5; p++) m = fmaxf(m, elw[p]);
        float e[5], s = 0.f;
        for (int p = 0; p < 5; p++) { e[p] = expf(elw[p] - m); s += e[p]; }
        float inv = 1.f / s;
        for (int p = 0; p < 5; p++) { wsm[p] = e[p] * inv; out_w[p] = e[p] * inv; }
    }
}

__global__ void combine_w5_k(const float* __restrict__ ew, const float* __restrict__ wsm,
                             float* __restrict__ w5)
{
    int i = blockIdx.x * blockDim.x + threadIdx.x;   // D*D
    float w0 = wsm[0], w1 = wsm[1], w2 = wsm[2], w3 = wsm[3], w4 = wsm[4];
    const size_t DD = (size_t)1024 * 1024;
    float v = w0 * ew[i] + w1 * ew[DD + i] + w2 * ew[2 * DD + i]
            + w3 * ew[3 * DD + i] + w4 * ew[4 * DD + i];
    w5[i] = v;
}

__global__ void combine_b5_k(const float* __restrict__ eb, const float* __restrict__ wsm,
                             float* __restrict__ b5)
{
    int i = blockIdx.x * blockDim.x + threadIdx.x;   // D
    float v = 0.f;
    for (int p = 0; p < 5; p++) v += wsm[p] * eb[p * 1024 + i];
    b5[i] = v;
}

// mech[r] = sigmoid(dot(mh[r,:512], mw2) + mb2); one warp per row.
__global__ void mech_out_k(const float* __restrict__ mh, const float* __restrict__ mw2,
                           const float* __restrict__ mb2, float* __restrict__ mech,
                           float* __restrict__ out_mech)
{
    int row  = blockIdx.x * 8 + (threadIdx.x >> 5);
    int lane = threadIdx.x & 31;
    const float* r = mh + (size_t)row * 512;
    float s = 0.f;
#pragma unroll
    for (int c = lane; c < 512; c += 32) s = fmaf(r[c], mw2[c], s);
#pragma unroll
    for (int off = 16; off > 0; off >>= 1) s += __shfl_xor_sync(0xffffffffu, s, off);
    if (lane == 0) {
        float t = s + mb2[0];
        float m = 1.f / (1.f + expf(-t));
        mech[row] = m;
        out_mech[row] = m;
    }
}

// ---------------------------------------------------------------------------
// Flash attention (fp32). Per block: one (b,h) and a 64-row Q tile.
// scores = (Q K^T / 8) * (1 + mech[key]); online softmax; ctx = P V.
// block = 256 threads as 16x16, each owning 4x4 fragments.
// ---------------------------------------------------------------------------
__global__ void __launch_bounds__(256, 2)
attn_k(const float* __restrict__ Q, const float* __restrict__ Kp,
       const float* __restrict__ Vp, const float* __restrict__ mech,
       float* __restrict__ Octx)
{
    extern __shared__ float sm[];
    const int PAD = 68;
    float* QsT  = sm;                 // [64][68] transposed (d major)
    float* KsT  = QsT + 64 * PAD;     // [64][68] transposed
    float* Vs   = KsT + 64 * PAD;     // [64][68]
    float* PsT  = Vs  + 64 * PAD;     // [64][68] (k major)
    float* red  = PsT + 64 * PAD;     // [64][16]
    float* red2 = red + 64 * 16;      // [64][16]
    float* m_i  = red2 + 64 * 16;     // [64]
    float* l_i  = m_i + 64;           // [64]
    float* alp  = l_i + 64;           // [64]
    float* fac  = alp + 64;           // [64]

    const int tid = threadIdx.x;
    const int tx = tid & 15, ty = tid >> 4;
    const int bh = blockIdx.y;
    const int b = bh >> 4, h = bh & 15;
    const int q0 = blockIdx.x * 64;
    const size_t base = (size_t)b * Sc * Dc + (size_t)h * 64;

    // Load Q tile (transposed into QsT[d][q])
    {
        int r = tid >> 2;
        int d0 = (tid & 3) * 16;
        const float* qp = Q + base + (size_t)(q0 + r) * Dc + d0;
#pragma unroll
        for (int u = 0; u < 4; u++) {
            float4 v = *(const float4*)(qp + u * 4);
            QsT[(d0 + u * 4 + 0) * PAD + r] = v.x;
            QsT[(d0 + u * 4 + 1) * PAD + r] = v.y;
            QsT[(d0 + u * 4 + 2) * PAD + r] = v.z;
            QsT[(d0 + u * 4 + 3) * PAD + r] = v.w;
        }
    }
    if (tid < 64) { m_i[tid] = -1e30f; l_i[tid] = 0.f; }
    float acc[4][4];
#pragma unroll
    for (int i = 0; i < 4; i++)
#pragma unroll
        for (int j = 0; j < 4; j++) acc[i][j] = 0.f;
    __syncthreads();

    for (int kt = 0; kt < 16; kt++) {
        const int k0 = kt * 64;
        // Load K (transposed), V (direct), mech factors
        {
            int r = tid >> 2;
            int d0 = (tid & 3) * 16;
            const float* kp = Kp + base + (size_t)(k0 + r) * Dc + d0;
            const float* vp = Vp + base + (size_t)(k0 + r) * Dc + d0;
#pragma unroll
            for (int u = 0; u < 4; u++) {
                float4 v = *(const float4*)(kp + u * 4);
                KsT[(d0 + u * 4 + 0) * PAD + r] = v.x;
                KsT[(d0 + u * 4 + 1) * PAD + r] = v.y;
                KsT[(d0 + u * 4 + 2) * PAD + r] = v.z;
                KsT[(d0 + u * 4 + 3) * PAD + r] = v.w;
                float4 w = *(const float4*)(vp + u * 4);
                *(float4*)&Vs[r * PAD + d0 + u * 4] = w;
            }
        }
        if (tid < 64) fac[tid] = 1.f + mech[(size_t)b * Sc + k0 + tid];
        __syncthreads();

        // S tile = Q K^T  (each thread 4x4)
        float s[4][4];
#pragma unroll
        for (int i = 0; i < 4; i++)
#pragma unroll
            for (int j = 0; j < 4; j++) s[i][j] = 0.f;
#pragma unroll 4
        for (int d = 0; d < 64; d++) {
            float4 qv = *(const float4*)&QsT[d * PAD + ty * 4];
            float4 kv = *(const float4*)&KsT[d * PAD + tx * 4];
            float qa[4] = {qv.x, qv.y, qv.z, qv.w};
            float ka[4] = {kv.x, kv.y, kv.z, kv.w};
#pragma unroll
            for (int i = 0; i < 4; i++)
#pragma unroll
                for (int j = 0; j < 4; j++)
                    s[i][j] = fmaf(qa[i], ka[j], s[i][j]);
        }
        float fj[4];
#pragma unroll
        for (int j = 0; j < 4; j++) fj[j] = 0.125f * fac[tx * 4 + j];
#pragma unroll
        for (int i = 0; i < 4; i++)
#pragma unroll
            for (int j = 0; j < 4; j++) s[i][j] *= fj[j];

        // partial row max
#pragma unroll
        for (int i = 0; i < 4; i++) {
            float pm = fmaxf(fmaxf(s[i][0], s[i][1]), fmaxf(s[i][2], s[i][3]));
            red[(ty * 4 + i) * 16 + tx] = pm;
        }
        __syncthreads();

        float mnew[4];
#pragma unroll
        for (int i = 0; i < 4; i++) {
            int r = ty * 4 + i;
            float m = m_i[r];
#pragma unroll
            for (int t = 0; t < 16; t++) m = fmaxf(m, red[r * 16 + t]);
            mnew[i] = m;
        }
        // p = exp(s - mnew), write P (transposed, k major) + partial sums
        float psum[4] = {0.f, 0.f, 0.f, 0.f};
#pragma unroll
        for (int i = 0; i < 4; i++) {
#pragma unroll
            for (int j = 0; j < 4; j++) {
                float p = expf(s[i][j] - mnew[i]);
                PsT[(tx * 4 + j) * PAD + ty * 4 + i] = p;
                psum[i] += p;
            }
            red2[(ty * 4 + i) * 16 + tx] = psum[i];
        }
        __syncthreads();

        if (tx == 0) {
#pragma unroll
            for (int i = 0; i < 4; i++) {
                int r = ty * 4 + i;
                float ls = 0.f;
#pragma unroll
                for (int t = 0; t < 16; t++) ls += red2[r * 16 + t];
                float a = expf(m_i[r] - mnew[i]);
                l_i[r] = l_i[r] * a + ls;
                m_i[r] = mnew[i];
                alp[r] = a;
            }
        }
        __syncthreads();

        float av[4];
#pragma unroll
        for (int i = 0; i < 4; i++) av[i] = alp[ty * 4 + i];
#pragma unroll
        for (int i = 0; i < 4; i++)
#pragma unroll
            for (int j = 0; j < 4; j++) acc[i][j] *= av[i];

        // acc += P V
#pragma unroll 4
        for (int k = 0; k < 64; k++) {
            float4 pv = *(const float4*)&PsT[k * PAD + ty * 4];
            float4 vv = *(const float4*)&Vs[k * PAD + tx * 4];
            float pa[4] = {pv.x, pv.y, pv.z, pv.w};
            float va[4] = {vv.x, vv.y, vv.z, vv.w};
#pragma unroll
            for (int i = 0; i < 4; i++)
#pragma unroll
                for (int j = 0; j < 4; j++)
                    acc[i][j] = fmaf(pa[i], va[j], acc[i][j]);
        }
        __syncthreads();
    }

    // epilogue: O = acc / l
#pragma unroll
    for (int i = 0; i < 4; i++) {
        int r = ty * 4 + i;
        float inv = 1.f / l_i[r];
        float4 o;
        o.x = acc[i][0] * inv;
        o.y = acc[i][1] * inv;
        o.z = acc[i][2] * inv;
        o.w = acc[i][3] * inv;
        *(float4*)&Octx[base + (size_t)(q0 + r) * Dc + tx * 4] = o;
    }
}

// ---------------------------------------------------------------------------
// Host launcher
// ---------------------------------------------------------------------------
extern "C" void kernel_launch(void* const* d_in, const int* in_sizes, int n_in,
                              void* d_out, int out_size)
{
    (void)in_sizes; (void)n_in; (void)out_size;
    const float* x_in = (const float*)d_in[0];
    const float* pos  = (const float*)d_in[1];
    const float* tim  = (const float*)d_in[2];
    const float* wi   = (const float*)d_in[3];
    const float* bi   = (const float*)d_in[4];
    const float* g1   = (const float*)d_in[5];
    const float* be1  = (const float*)d_in[6];
    const float* g2   = (const float*)d_in[7];
    const float* be2  = (const float*)d_in[8];
    const float* g3   = (const float*)d_in[9];
    const float* be3  = (const float*)d_in[10];
    const float* qw   = (const float*)d_in[11];
    const float* qb   = (const float*)d_in[12];
    const float* kw   = (const float*)d_in[13];
    const float* kb   = (const float*)d_in[14];
    const float* vw   = (const float*)d_in[15];
    const float* vb   = (const float*)d_in[16];
    const float* ow   = (const float*)d_in[17];
    const float* ob   = (const float*)d_in[18];
    const float* mw1  = (const float*)d_in[19];
    const float* mb1  = (const float*)d_in[20];
    const float* mw2  = (const float*)d_in[21];
    const float* mb2  = (const float*)d_in[22];
    const float* ew   = (const float*)d_in[23];
    const float* eb   = (const float*)d_in[24];
    const float* elw  = (const float*)d_in[25];
    const float* fw1  = (const float*)d_in[26];
    const float* fb1  = (const float*)d_in[27];
    const float* fw2  = (const float*)d_in[28];
    const float* fb2  = (const float*)d_in[29];

    float* out = (float*)d_out;
    float* out_mech = out + NXD;          // 8,388,608
    float* out_w    = out + NXD + BS;     // +8192

    float* base = nullptr;
    cudaGetSymbolAddress((void**)&base, g_buf);
    float* gx   = base + OFF_X;
    float* gh   = base + OFF_H;
    float* gq   = base + OFF_Q;
    float* gk   = base + OFF_K;
    float* gv   = base + OFF_V;
    float* gctx = base + OFF_CTX;
    float* gmh  = base + OFF_MH;
    float* gmech= base + OFF_MECH;
    float* gpe  = base + OFF_PE;
    float* gpep = base + OFF_PEP;
    float* gw5  = base + OFF_W5;
    float* gb5  = base + OFF_B5;
    float* gwsm = base + OFF_WSM;
    float* gffh = base + OFF_FFH;

    const int ATTN_SMEM = (4 * 64 * 68 + 2 * 64 * 16 + 4 * 64) * (int)sizeof(float);
    cudaFuncSetAttribute(attn_k, cudaFuncAttributeMaxDynamicSharedMemorySize, ATTN_SMEM);

    // 1) positional/timing embedding: pe = concat(pos, time); x = x_in + pe@wi + bi
    build_pe_k<<<(Sc * Dc) / 256, 256>>>(pos, tim, gpe);
    tgemm_k<<<dim3(Dc / 128, Sc / 128), 256>>>(gpe, wi, bi, nullptr, gpep, Sc, Dc, Dc, 0);
    add_pe_k<<<(unsigned)(NXD / 256), 256>>>(x_in, gpep, gx);

    // 2) norm1 -> h
    layernorm_k<<<BS, 256>>>(gx, g1, be1, gh);

    // 3) q,k,v projections
    tgemm_k<<<dim3(Dc / 128, BS / 128), 256>>>(gh, qw, qb, nullptr, gq, BS, Dc, Dc, 0);
    tgemm_k<<<dim3(Dc / 128, BS / 128), 256>>>(gh, kw, kb, nullptr, gk, BS, Dc, Dc, 0);
    tgemm_k<<<dim3(Dc / 128, BS / 128), 256>>>(gh, vw, vb, nullptr, gv, BS, Dc, Dc, 0);

    // 4) mechanism MLP: gelu(h@mw1+mb1) @ mw2 + mb2 -> sigmoid
    tgemm_k<<<dim3(512 / 128, BS / 128), 256>>>(gh, mw1, mb1, nullptr, gmh, BS, 512, Dc, 1);
    mech_out_k<<<BS / 8, 256>>>(gmh, mw2, mb2, gmech, out_mech);

    // 5) flash attention with mechanism key-weighting
    attn_k<<<dim3(Sc / 64, Bc * Hc), 256, ATTN_SMEM>>>(gq, gk, gv, gmech, gctx);

    // 6) output projection + residual
    tgemm_k<<<dim3(Dc / 128, BS / 128), 256>>>(gctx, ow, ob, gx, gx, BS, Dc, Dc, 0);

    // 7) five elements: fold 5 projections into one via softmax(elw) weights
    layernorm_k<<<BS, 256>>>(gx, g2, be2, gh);
    softmax5_k<<<1, 32>>>(elw, gwsm, out_w);
    combine_w5_k<<<(Dc * Dc) / 256, 256>>>(ew, gwsm, gw5);
    combine_b5_k<<<Dc / 256, 256>>>(eb, gwsm, gb5);
    tgemm_k<<<dim3(Dc / 128, BS / 128), 256>>>(gh, gw5, gb5, gx, gx, BS, Dc, Dc, 0);

    // 8) FFN
    layernorm_k<<<BS, 256>>>(gx, g3, be3, gh);
    tgemm_k<<<dim3(DFFc / 128, BS / 128), 256>>>(gh, fw1, fb1, nullptr, gffh, BS, DFFc, Dc, 1);
    // final: write x directly into d_out
    tgemm_k<<<dim3(Dc / 128, BS / 128), 256>>>(gffh, fw2, fb2, gx, out, BS, Dc, DFFc, 0);
}

// round 5
// speedup vs baseline: 2.7521x; 1.3218x over previous
#include <cuda_runtime.h>
#include <math.h>
#include <stdint.h>

// ---------------------------------------------------------------------------
// MechanismTransformerBlock  B=8 S=1024 D=1024 H=16 DH=64 DFF=4096
// TF32 tensor-core GEMM (mma.sync m16n8k8, 128x128x16 tiles, double-buffered)
// + TF32 tensor-core flash attention (mech factor folded into K operand).
// ---------------------------------------------------------------------------

namespace {
constexpr int Bc = 8, Sc = 1024, Dc = 1024, Hc = 16, DFFc = 4096;
constexpr int BS = Bc * Sc;                       // 8192 rows
constexpr size_t NXD = (size_t)BS * Dc;           // 8,388,608

constexpr size_t OFF_X    = 0;
constexpr size_t OFF_H    = OFF_X   + NXD;
constexpr size_t OFF_QKV  = OFF_H   + NXD;                    // BS x 3072
constexpr size_t OFF_CTX  = OFF_QKV + 3 * NXD;
constexpr size_t OFF_MH   = OFF_CTX + NXD;                    // BS x 512
constexpr size_t OFF_MECH = OFF_MH  + (size_t)BS * 512;       // BS
constexpr size_t OFF_PE   = OFF_MECH+ (size_t)BS;             // S x D
constexpr size_t OFF_PEP  = OFF_PE  + (size_t)Sc * Dc;        // S x D
constexpr size_t OFF_W5   = OFF_PEP + (size_t)Sc * Dc;        // D x D
constexpr size_t OFF_B5   = OFF_W5  + (size_t)Dc * Dc;        // D
constexpr size_t OFF_WSM  = OFF_B5  + Dc;                     // 8
constexpr size_t OFF_WQKV = OFF_WSM + 8;                      // D x 3D
constexpr size_t OFF_BQKV = OFF_WQKV + (size_t)Dc * 3 * Dc;   // 3D
constexpr size_t OFF_FFH  = OFF_BQKV + 3 * Dc;                // BS x DFF
constexpr size_t TOTALF   = OFF_FFH + (size_t)BS * DFFc;
}

__device__ float g_buf[TOTALF];

__device__ __forceinline__ float gelu_exact(float v) {
    return 0.5f * v * (1.0f + erff(v * 0.70710678118654752440f));
}

__device__ __forceinline__ float f2tf32(float f) {
    uint32_t r;
    asm("cvt.rna.tf32.f32 %0, %1;" : "=r"(r) : "f"(f));
    return __uint_as_float(r);
}

__device__ __forceinline__ void mma_tf32(float* c, const uint32_t* a, const uint32_t* b) {
    asm volatile(
        "mma.sync.aligned.m16n8k8.row.col.f32.tf32.tf32.f32 "
        "{%0,%1,%2,%3}, {%4,%5,%6,%7}, {%8,%9}, {%0,%1,%2,%3};\n"
        : "+f"(c[0]), "+f"(c[1]), "+f"(c[2]), "+f"(c[3])
        : "r"(a[0]), "r"(a[1]), "r"(a[2]), "r"(a[3]), "r"(b[0]), "r"(b[1]));
}

// ---------------------------------------------------------------------------
// TF32 GEMM: C[M,N] = act(A[M,K] @ B[K,N] + bias) + resid   (row-major).
// 128x128 block tile, BK=16, 256 threads = 8 warps (4M x 2N), warp tile 32x64.
// ---------------------------------------------------------------------------
#define GP 136

__global__ void __launch_bounds__(256, 2)
tgemm_k(const float* __restrict__ A, const float* __restrict__ Bm,
        const float* __restrict__ bias, const float* __restrict__ resid,
        float* __restrict__ C, int M, int N, int K, int act)
{
    __shared__ float As[2][16][GP];
    __shared__ float Bs[2][16][GP];

    const int tid = threadIdx.x;
    const int w = tid >> 5, l = tid & 31;
    const int wm = (w & 3) * 32;          // warp M offset in block tile
    const int wn = (w >> 2) * 64;         // warp N offset in block tile
    const int g = l >> 2, t = l & 3;      // mma lane decomposition
    const int bn = blockIdx.x, bm = blockIdx.y;
    const float* Ab = A + (size_t)bm * 128 * K;
    const float* Bb = Bm + (size_t)bn * 128;

    const int arow = tid >> 1;            // 0..127
    const int acol = (tid & 1) * 8;       // 0 or 8
    const int brow = tid >> 4;            // 0..15
    const int bcol = (tid & 15) * 8;      // 0..120

    float acc[2][8][4];
#pragma unroll
    for (int i = 0; i < 2; i++)
#pragma unroll
        for (int j = 0; j < 8; j++)
#pragma unroll
            for (int r = 0; r < 4; r++) acc[i][j][r] = 0.f;

    // ---- prologue: load tile 0 into buffer 0 ----
    {
        const float* Ap = Ab + (size_t)arow * K + acol;
        float4 a0 = *(const float4*)Ap;
        float4 a1 = *(const float4*)(Ap + 4);
        As[0][acol + 0][arow] = f2tf32(a0.x);
        As[0][acol + 1][arow] = f2tf32(a0.y);
        As[0][acol + 2][arow] = f2tf32(a0.z);
        As[0][acol + 3][arow] = f2tf32(a0.w);
        As[0][acol + 4][arow] = f2tf32(a1.x);
        As[0][acol + 5][arow] = f2tf32(a1.y);
        As[0][acol + 6][arow] = f2tf32(a1.z);
        As[0][acol + 7][arow] = f2tf32(a1.w);
        const float* Bp = Bb + (size_t)brow * N + bcol;
        float4 b0 = *(const float4*)Bp;
        float4 b1 = *(const float4*)(Bp + 4);
        float4 c0 = make_float4(f2tf32(b0.x), f2tf32(b0.y), f2tf32(b0.z), f2tf32(b0.w));
        float4 c1 = make_float4(f2tf32(b1.x), f2tf32(b1.y), f2tf32(b1.z), f2tf32(b1.w));
        *(float4*)&Bs[0][brow][bcol]     = c0;
        *(float4*)&Bs[0][brow][bcol + 4] = c1;
    }
    __syncthreads();

    int cur = 0;
    for (int k0 = 0; k0 < K; k0 += 16) {
        const bool hn = (k0 + 16) < K;
        float4 na0, na1, nb0, nb1;
        if (hn) {
            const float* Ap = Ab + (size_t)arow * K + (k0 + 16) + acol;
            na0 = *(const float4*)Ap;
            na1 = *(const float4*)(Ap + 4);
            const float* Bp = Bb + (size_t)(k0 + 16 + brow) * N + bcol;
            nb0 = *(const float4*)Bp;
            nb1 = *(const float4*)(Bp + 4);
        }

#pragma unroll
        for (int ks = 0; ks < 2; ks++) {
            const int kb = ks * 8;
            uint32_t af[2][4], bf[8][2];
#pragma unroll
            for (int i = 0; i < 2; i++) {
                const float* p0 = &As[cur][kb + t][wm + i * 16 + g];
                const float* p1 = &As[cur][kb + t + 4][wm + i * 16 + g];
                af[i][0] = __float_as_uint(p0[0]);
                af[i][1] = __float_as_uint(p0[8]);
                af[i][2] = __float_as_uint(p1[0]);
                af[i][3] = __float_as_uint(p1[8]);
            }
#pragma unroll
            for (int j = 0; j < 8; j++) {
                bf[j][0] = __float_as_uint(Bs[cur][kb + t][wn + j * 8 + g]);
                bf[j][1] = __float_as_uint(Bs[cur][kb + t + 4][wn + j * 8 + g]);
            }
#pragma unroll
            for (int i = 0; i < 2; i++)
#pragma unroll
                for (int j = 0; j < 8; j++)
                    mma_tf32(acc[i][j], af[i], bf[j]);
        }

        if (hn) {
            int nxt = cur ^ 1;
            As[nxt][acol + 0][arow] = f2tf32(na0.x);
            As[nxt][acol + 1][arow] = f2tf32(na0.y);
            As[nxt][acol + 2][arow] = f2tf32(na0.z);
            As[nxt][acol + 3][arow] = f2tf32(na0.w);
            As[nxt][acol + 4][arow] = f2tf32(na1.x);
            As[nxt][acol + 5][arow] = f2tf32(na1.y);
            As[nxt][acol + 6][arow] = f2tf32(na1.z);
            As[nxt][acol + 7][arow] = f2tf32(na1.w);
            float4 c0 = make_float4(f2tf32(nb0.x), f2tf32(nb0.y), f2tf32(nb0.z), f2tf32(nb0.w));
            float4 c1 = make_float4(f2tf32(nb1.x), f2tf32(nb1.y), f2tf32(nb1.z), f2tf32(nb1.w));
            *(float4*)&Bs[nxt][brow][bcol]     = c0;
            *(float4*)&Bs[nxt][brow][bcol + 4] = c1;
        }
        __syncthreads();
        cur ^= 1;
    }

    // ---- epilogue ----
#pragma unroll
    for (int i = 0; i < 2; i++) {
        int row0 = bm * 128 + wm + i * 16 + g;
        int row1 = row0 + 8;
        size_t ro0 = (size_t)row0 * N;
        size_t ro1 = (size_t)row1 * N;
#pragma unroll
        for (int j = 0; j < 8; j++) {
            int col = bn * 128 + wn + j * 8 + 2 * t;
            float v0 = acc[i][j][0], v1 = acc[i][j][1];
            float v2 = acc[i][j][2], v3 = acc[i][j][3];
            if (bias) {
                float b0 = bias[col], b1 = bias[col + 1];
                v0 += b0; v1 += b1; v2 += b0; v3 += b1;
            }
            if (act == 1) {
                v0 = gelu_exact(v0); v1 = gelu_exact(v1);
                v2 = gelu_exact(v2); v3 = gelu_exact(v3);
            }
            if (resid) {
                v0 += resid[ro0 + col]; v1 += resid[ro0 + col + 1];
                v2 += resid[ro1 + col]; v3 += resid[ro1 + col + 1];
            }
            *(float2*)&C[ro0 + col] = make_float2(v0, v1);
            *(float2*)&C[ro1 + col] = make_float2(v2, v3);
        }
    }
}

// ---------------------------------------------------------------------------
// TF32 flash attention.  QKV packed [BS][3072] (Q|K|V per 1024 slice).
// Per block: one (b,h), Q tile 128 rows; K/V tiles of 64 keys, 16 iterations.
// scores = Q . (K * 0.125*(1+mech_k))^T   (mech factor folded into K smem).
// Online softmax fully in registers; P moved C-layout -> A-layout via quad
// shuffles.  8 warps; warp w owns Q rows w*16..w*16+15.
// ---------------------------------------------------------------------------
#define AP 68

__global__ void __launch_bounds__(256)
attn_tc_k(const float* __restrict__ QKV, const float* __restrict__ mech,
          float* __restrict__ Octx)
{
    extern __shared__ float sma[];
    float* Qs = sma;               // [128][AP]   Q rows (tf32)
    float* Ks = Qs + 128 * AP;     // [64][AP]    K rows, pre-scaled (tf32)
    float* Vt = Ks + 64 * AP;      // [64][AP]    Vt[d][key] (tf32)

    const int tid = threadIdx.x;
    const int w = tid >> 5, l = tid & 31;
    const int g = l >> 2, t = l & 3;
    const int bh = blockIdx.y;
    const int b = bh >> 4, h = bh & 15;
    const int q0 = blockIdx.x * 128;
    const int qr = w * 16;                      // warp's row base in tile

    // ---- load Q tile (rows q0..q0+127) ----
    {
        int r = tid >> 2;                       // 0..63
        int c = (tid & 3) * 16;
#pragma unroll
        for (int half = 0; half < 2; half++) {
            int rr = r + half * 64;
            const float* qp = QKV + ((size_t)b * 1024 + q0 + rr) * 3072 + h * 64 + c;
#pragma unroll
            for (int u = 0; u < 4; u++) {
                float4 v = *(const float4*)(qp + u * 4);
                float4 cv = make_float4(f2tf32(v.x), f2tf32(v.y), f2tf32(v.z), f2tf32(v.w));
                *(float4*)&Qs[rr * AP + c + u * 4] = cv;
            }
        }
    }

    float m0 = -1e30f, m1 = -1e30f, l0 = 0.f, l1 = 0.f;
    float acc[8][4];
#pragma unroll
    for (int e = 0; e < 8; e++)
#pragma unroll
        for (int r = 0; r < 4; r++) acc[e][r] = 0.f;
    __syncthreads();

    for (int kt = 0; kt < 16; kt++) {
        const int k0 = kt * 64;
        // ---- load K (scaled by 0.125*(1+mech)) and V (transposed) ----
        {
            int r = tid >> 2;                   // key row 0..63
            int c = (tid & 3) * 16;
            size_t rowb = ((size_t)b * 1024 + k0 + r) * 3072 + h * 64;
            float fac = 0.125f * (1.f + mech[(size_t)b * 1024 + k0 + r]);
            const float* kp = QKV + rowb + 1024 + c;
            const float* vp = QKV + rowb + 2048 + c;
#pragma unroll
            for (int u = 0; u < 4; u++) {
                float4 kv = *(const float4*)(kp + u * 4);
                float4 ck = make_float4(f2tf32(kv.x * fac), f2tf32(kv.y * fac),
                                        f2tf32(kv.z * fac), f2tf32(kv.w * fac));
                *(float4*)&Ks[r * AP + c + u * 4] = ck;
                float4 vv = *(const float4*)(vp + u * 4);
                Vt[(c + u * 4 + 0) * AP + r] = f2tf32(vv.x);
                Vt[(c + u * 4 + 1) * AP + r] = f2tf32(vv.y);
                Vt[(c + u * 4 + 2) * AP + r] = f2tf32(vv.z);
                Vt[(c + u * 4 + 3) * AP + r] = f2tf32(vv.w);
            }
        }
        __syncthreads();

        // ---- S = Q K'^T  (warp: 16 rows x 64 keys, 8 n-tiles) ----
        float s[8][4];
#pragma unroll
        for (int j = 0; j < 8; j++)
#pragma unroll
            for (int r = 0; r < 4; r++) s[j][r] = 0.f;
#pragma unroll
        for (int kd = 0; kd < 8; kd++) {
            uint32_t a[4];
            const float* p0 = &Qs[(qr + g) * AP + kd * 8 + t];
            const float* p1 = &Qs[(qr + 8 + g) * AP + kd * 8 + t];
            a[0] = __float_as_uint(p0[0]);
            a[1] = __float_as_uint(p1[0]);
            a[2] = __float_as_uint(p0[4]);
            a[3] = __float_as_uint(p1[4]);
#pragma unroll
            for (int j = 0; j < 8; j++) {
                uint32_t bb[2];
                bb[0] = __float_as_uint(Ks[(j * 8 + g) * AP + kd * 8 + t]);
                bb[1] = __float_as_uint(Ks[(j * 8 + g) * AP + kd * 8 + t + 4]);
                mma_tf32(s[j], a, bb);
            }
        }

        // ---- online softmax (register-resident; quad reductions) ----
        float mx0 = -1e30f, mx1 = -1e30f;
#pragma unroll
        for (int j = 0; j < 8; j++) {
            mx0 = fmaxf(mx0, fmaxf(s[j][0], s[j][1]));
            mx1 = fmaxf(mx1, fmaxf(s[j][2], s[j][3]));
        }
        mx0 = fmaxf(mx0, __shfl_xor_sync(0xffffffffu, mx0, 1));
        mx0 = fmaxf(mx0, __shfl_xor_sync(0xffffffffu, mx0, 2));
        mx1 = fmaxf(mx1, __shfl_xor_sync(0xffffffffu, mx1, 1));
        mx1 = fmaxf(mx1, __shfl_xor_sync(0xffffffffu, mx1, 2));
        float mn0 = fmaxf(m0, mx0), mn1 = fmaxf(m1, mx1);
        float al0 = __expf(m0 - mn0), al1 = __expf(m1 - mn1);
        float sum0 = 0.f, sum1 = 0.f;
#pragma unroll
        for (int j = 0; j < 8; j++) {
            s[j][0] = __expf(s[j][0] - mn0);
            s[j][1] = __expf(s[j][1] - mn0);
            s[j][2] = __expf(s[j][2] - mn1);
            s[j][3] = __expf(s[j][3] - mn1);
            sum0 += s[j][0] + s[j][1];
            sum1 += s[j][2] + s[j][3];
        }
        sum0 += __shfl_xor_sync(0xffffffffu, sum0, 1);
        sum0 += __shfl_xor_sync(0xffffffffu, sum0, 2);
        sum1 += __shfl_xor_sync(0xffffffffu, sum1, 1);
        sum1 += __shfl_xor_sync(0xffffffffu, sum1, 2);
        l0 = l0 * al0 + sum0;
        l1 = l1 * al1 + sum1;
        m0 = mn0; m1 = mn1;
#pragma unroll
        for (int e = 0; e < 8; e++) {
            acc[e][0] *= al0; acc[e][1] *= al0;
            acc[e][2] *= al1; acc[e][3] *= al1;
        }

        // ---- acc += P V : shuffle P from C-layout to A-layout per k-tile ----
        const int s0l = (l & 28) | (t >> 1);
        const int s1l = s0l + 2;
        const bool sel = (t & 1);
#pragma unroll
        for (int j = 0; j < 8; j++) {
            uint32_t p0 = __float_as_uint(f2tf32(s[j][0]));
            uint32_t p1 = __float_as_uint(f2tf32(s[j][1]));
            uint32_t p2 = __float_as_uint(f2tf32(s[j][2]));
            uint32_t p3 = __float_as_uint(f2tf32(s[j][3]));
            uint32_t x0 = __shfl_sync(0xffffffffu, p0, s0l);
            uint32_t x1 = __shfl_sync(0xffffffffu, p1, s0l);
            uint32_t x2 = __shfl_sync(0xffffffffu, p2, s0l);
            uint32_t x3 = __shfl_sync(0xffffffffu, p3, s0l);
            uint32_t y0 = __shfl_sync(0xffffffffu, p0, s1l);
            uint32_t y1 = __shfl_sync(0xffffffffu, p1, s1l);
            uint32_t y2 = __shfl_sync(0xffffffffu, p2, s1l);
            uint32_t y3 = __shfl_sync(0xffffffffu, p3, s1l);
            uint32_t a[4];
            a[0] = sel ? x1 : x0;   // P(g,      j*8 + t)
            a[1] = sel ? x3 : x2;   // P(g+8,    j*8 + t)
            a[2] = sel ? y1 : y0;   // P(g,      j*8 + t+4)
            a[3] = sel ? y3 : y2;   // P(g+8,    j*8 + t+4)
#pragma unroll
            for (int e = 0; e < 8; e++) {
                uint32_t bb[2];
                bb[0] = __float_as_uint(Vt[(e * 8 + g) * AP + j * 8 + t]);
                bb[1] = __float_as_uint(Vt[(e * 8 + g) * AP + j * 8 + t + 4]);
                mma_tf32(acc[e], a, bb);
            }
        }
        __syncthreads();
    }

    // ---- epilogue: O = acc / l ----
    float inv0 = 1.f / l0, inv1 = 1.f / l1;
    size_t o0 = ((size_t)b * 1024 + q0 + qr + g) * 1024 + h * 64;
    size_t o1 = o0 + (size_t)8 * 1024;
#pragma unroll
    for (int e = 0; e < 8; e++) {
        *(float2*)&Octx[o0 + e * 8 + 2 * t] = make_float2(acc[e][0] * inv0, acc[e][1] * inv0);
        *(float2*)&Octx[o1 + e * 8 + 2 * t] = make_float2(acc[e][2] * inv1, acc[e][3] * inv1);
    }
}

// ---------------------------------------------------------------------------
// LayerNorm over last dim (1024). One block (256 threads) per row.
// ---------------------------------------------------------------------------
__global__ void layernorm_k(const float* __restrict__ x, const float* __restrict__ g,
                            const float* __restrict__ b, float* __restrict__ o)
{
    int row = blockIdx.x;
    const float4* xr = (const float4*)(x + (size_t)row * 1024);
    float4 v = xr[threadIdx.x];
    float s  = v.x + v.y + v.z + v.w;
    float ss = fmaf(v.x, v.x, fmaf(v.y, v.y, fmaf(v.z, v.z, v.w * v.w)));
#pragma unroll
    for (int off = 16; off > 0; off >>= 1) {
        s  += __shfl_xor_sync(0xffffffffu, s,  off);
        ss += __shfl_xor_sync(0xffffffffu, ss, off);
    }
    __shared__ float ws[8], wss[8];
    __shared__ float s_mean, s_inv;
    int w = threadIdx.x >> 5, ln = threadIdx.x & 31;
    if (ln == 0) { ws[w] = s; wss[w] = ss; }
    __syncthreads();
    if (threadIdx.x == 0) {
        float S = 0.f, SS = 0.f;
#pragma unroll
        for (int i = 0; i < 8; i++) { S += ws[i]; SS += wss[i]; }
        float mean = S * (1.f / 1024.f);
        float var  = SS * (1.f / 1024.f) - mean * mean;
        s_mean = mean;
        s_inv  = rsqrtf(var + 1e-5f);
    }
    __syncthreads();
    float mean = s_mean, inv = s_inv;
    float4 gv = ((const float4*)g)[threadIdx.x];
    float4 bv = ((const float4*)b)[threadIdx.x];
    float4 r;
    r.x = (v.x - mean) * inv * gv.x + bv.x;
    r.y = (v.y - mean) * inv * gv.y + bv.y;
    r.z = (v.z - mean) * inv * gv.z + bv.z;
    r.w = (v.w - mean) * inv * gv.w + bv.w;
    ((float4*)(o + (size_t)row * 1024))[threadIdx.x] = r;
}

// ---------------------------------------------------------------------------
// Small elementwise kernels
// ---------------------------------------------------------------------------
__global__ void build_pe_k(const float* __restrict__ pos, const float* __restrict__ tim,
                           float* __restrict__ pe)
{
    int i = blockIdx.x * blockDim.x + threadIdx.x;   // S*D = 1M
    int s = i >> 10, d = i & 1023;
    pe[i] = (d < 512) ? pos[s * 512 + d] : tim[s * 512 + (d - 512)];
}

__global__ void add_pe_k(const float* __restrict__ xin, const float* __restrict__ pep,
                         float* __restrict__ x)
{
    size_t i = (size_t)blockIdx.x * blockDim.x + threadIdx.x;  // B*S*D
    x[i] = xin[i] + pep[i & ((size_t)(1 << 20) - 1)];
}

__global__ void softmax5_k(const float* __restrict__ elw, float* __restrict__ wsm,
                           float* __restrict__ out_w)
{
    if (threadIdx.x == 0) {
        float m = elw[0];
        for (int p = 1; p < 5; p++) m = fmaxf(m, elw[p]);
        float e[5], s = 0.f;
        for (int p = 0; p < 5; p++) { e[p] = expf(elw[p] - m); s += e[p]; }
        float inv = 1.f / s;
        for (int p = 0; p < 5; p++) { wsm[p] = e[p] * inv; out_w[p] = e[p] * inv; }
    }
}

__global__ void combine_w5_k(const float* __restrict__ ew, const float* __restrict__ wsm,
                             float* __restrict__ w5)
{
    int i = blockIdx.x * blockDim.x + threadIdx.x;   // D*D
    float w0 = wsm[0], w1 = wsm[1], w2 = wsm[2], w3 = wsm[3], w4 = wsm[4];
    const size_t DD = (size_t)1024 * 1024;
    float v = w0 * ew[i] + w1 * ew[DD + i] + w2 * ew[2 * DD + i]
            + w3 * ew[3 * DD + i] + w4 * ew[4 * DD + i];
    w5[i] = v;
}

__global__ void combine_b5_k(const float* __restrict__ eb, const float* __restrict__ wsm,
                             float* __restrict__ b5)
{
    int i = blockIdx.x * blockDim.x + threadIdx.x;   // D
    float v = 0.f;
    for (int p = 0; p < 5; p++) v += wsm[p] * eb[p * 1024 + i];
    b5[i] = v;
}

// Pack qw|kw|vw -> [D][3D], qb|kb|vb -> [3D]
__global__ void pack_qkv_k(const float* __restrict__ qw, const float* __restrict__ kw,
                           const float* __restrict__ vw, const float* __restrict__ qb,
                           const float* __restrict__ kb, const float* __restrict__ vb,
                           float* __restrict__ wqkv, float* __restrict__ bqkv)
{
    int i = blockIdx.x * blockDim.x + threadIdx.x;   // D*D
    int k = i >> 10, n = i & 1023;
    size_t o = (size_t)k * 3072 + n;
    wqkv[o]        = qw[i];
    wqkv[o + 1024] = kw[i];
    wqkv[o + 2048] = vw[i];
    if (i < 1024) {
        bqkv[i]        = qb[i];
        bqkv[i + 1024] = kb[i];
        bqkv[i + 2048] = vb[i];
    }
}

// mech[r] = sigmoid(dot(mh[r,:512], mw2) + mb2); one warp per row.
__global__ void mech_out_k(const float* __restrict__ mh, const float* __restrict__ mw2,
                           const float* __restrict__ mb2, float* __restrict__ mech,
                           float* __restrict__ out_mech)
{
    int row  = blockIdx.x * 8 + (threadIdx.x >> 5);
    int lane = threadIdx.x & 31;
    const float* r = mh + (size_t)row * 512;
    float s = 0.f;
#pragma unroll
    for (int c = lane; c < 512; c += 32) s = fmaf(r[c], mw2[c], s);
#pragma unroll
    for (int off = 16; off > 0; off >>= 1) s += __shfl_xor_sync(0xffffffffu, s, off);
    if (lane == 0) {
        float t = s + mb2[0];
        float m = 1.f / (1.f + expf(-t));
        mech[row] = m;
        out_mech[row] = m;
    }
}

// ---------------------------------------------------------------------------
// Host launcher
// ---------------------------------------------------------------------------
extern "C" void kernel_launch(void* const* d_in, const int* in_sizes, int n_in,
                              void* d_out, int out_size)
{
    (void)in_sizes; (void)n_in; (void)out_size;
    const float* x_in = (const float*)d_in[0];
    const float* pos  = (const float*)d_in[1];
    const float* tim  = (const float*)d_in[2];
    const float* wi   = (const float*)d_in[3];
    const float* bi   = (const float*)d_in[4];
    const float* g1   = (const float*)d_in[5];
    const float* be1  = (const float*)d_in[6];
    const float* g2   = (const float*)d_in[7];
    const float* be2  = (const float*)d_in[8];
    const float* g3   = (const float*)d_in[9];
    const float* be3  = (const float*)d_in[10];
    const float* qw   = (const float*)d_in[11];
    const float* qb   = (const float*)d_in[12];
    const float* kw   = (const float*)d_in[13];
    const float* kb   = (const float*)d_in[14];
    const float* vw   = (const float*)d_in[15];
    const float* vb   = (const float*)d_in[16];
    const float* ow   = (const float*)d_in[17];
    const float* ob   = (const float*)d_in[18];
    const float* mw1  = (const float*)d_in[19];
    const float* mb1  = (const float*)d_in[20];
    const float* mw2  = (const float*)d_in[21];
    const float* mb2  = (const float*)d_in[22];
    const float* ew   = (const float*)d_in[23];
    const float* eb   = (const float*)d_in[24];
    const float* elw  = (const float*)d_in[25];
    const float* fw1  = (const float*)d_in[26];
    const float* fb1  = (const float*)d_in[27];
    const float* fw2  = (const float*)d_in[28];
    const float* fb2  = (const float*)d_in[29];

    float* out = (float*)d_out;
    float* out_mech = out + NXD;          // 8,388,608
    float* out_w    = out + NXD + BS;     // +8192

    float* base = nullptr;
    cudaGetSymbolAddress((void**)&base, g_buf);
    float* gx    = base + OFF_X;
    float* gh    = base + OFF_H;
    float* gqkv  = base + OFF_QKV;
    float* gctx  = base + OFF_CTX;
    float* gmh   = base + OFF_MH;
    float* gmech = base + OFF_MECH;
    float* gpe   = base + OFF_PE;
    float* gpep  = base + OFF_PEP;
    float* gw5   = base + OFF_W5;
    float* gb5   = base + OFF_B5;
    float* gwsm  = base + OFF_WSM;
    float* gwqkv = base + OFF_WQKV;
    float* gbqkv = base + OFF_BQKV;
    float* gffh  = base + OFF_FFH;

    const int ATTN_SMEM = 256 * AP * (int)sizeof(float);   // 69632 B
    cudaFuncSetAttribute(attn_tc_k, cudaFuncAttributeMaxDynamicSharedMemorySize, ATTN_SMEM);

    // 1) positional/timing embedding: pe = concat(pos, time); x = x_in + pe@wi + bi
    build_pe_k<<<(Sc * Dc) / 256, 256>>>(pos, tim, gpe);
    tgemm_k<<<dim3(Dc / 128, Sc / 128), 256>>>(gpe, wi, bi, nullptr, gpep, Sc, Dc, Dc, 0);
    add_pe_k<<<(unsigned)(NXD / 256), 256>>>(x_in, gpep, gx);

    // 2) norm1 -> h
    layernorm_k<<<BS, 256>>>(gx, g1, be1, gh);

    // 3) fused QKV projection (one GEMM, N=3072)
    pack_qkv_k<<<(Dc * Dc) / 256, 256>>>(qw, kw, vw, qb, kb, vb, gwqkv, gbqkv);
    tgemm_k<<<dim3(3 * Dc / 128, BS / 128), 256>>>(gh, gwqkv, gbqkv, nullptr, gqkv, BS, 3 * Dc, Dc, 0);

    // 4) mechanism MLP: gelu(h@mw1+mb1) @ mw2 + mb2 -> sigmoid
    tgemm_k<<<dim3(512 / 128, BS / 128), 256>>>(gh, mw1, mb1, nullptr, gmh, BS, 512, Dc, 1);
    mech_out_k<<<BS / 8, 256>>>(gmh, mw2, mb2, gmech, out_mech);

    // 5) flash attention (tensor cores; mech folded into K)
    attn_tc_k<<<dim3(Sc / 128, Bc * Hc), 256, ATTN_SMEM>>>(gqkv, gmech, gctx);

    // 6) output projection + residual
    tgemm_k<<<dim3(Dc / 128, BS / 128), 256>>>(gctx, ow, ob, gx, gx, BS, Dc, Dc, 0);

    // 7) five elements: fold 5 projections into one via softmax(elw) weights
    layernorm_k<<<BS, 256>>>(gx, g2, be2, gh);
    softmax5_k<<<1, 32>>>(elw, gwsm, out_w);
    combine_w5_k<<<(Dc * Dc) / 256, 256>>>(ew, gwsm, gw5);
    combine_b5_k<<<Dc / 256, 256>>>(eb, gwsm, gb5);
    tgemm_k<<<dim3(Dc / 128, BS / 128), 256>>>(gh, gw5, gb5, gx, gx, BS, Dc, Dc, 0);

    // 8) FFN
    layernorm_k<<<BS, 256>>>(gx, g3, be3, gh);
    tgemm_k<<<dim3(DFFc / 128, BS / 128), 256>>>(gh, fw1, fb1, nullptr, gffh, BS, DFFc, Dc, 1);
    // final: write x directly into d_out
    tgemm_k<<<dim3(Dc / 128, BS / 128), 256>>>(gffh, fw2, fb2, gx, out, BS, Dc, DFFc, 0);
}

// round 6
// speedup vs baseline: 4.1878x; 1.5217x over previous
#include <cuda_runtime.h>
#include <cuda_fp16.h>
#include <math.h>
#include <stdint.h>

// ---------------------------------------------------------------------------
// MechanismTransformerBlock  B=8 S=1024 D=1024 H=16 DH=64 DFF=4096
// fp16 tensor-core GEMM (ldmatrix + mma.m16n8k16, fp32 accum, 128x128x16,
// double-buffered, swizzled smem) + TF32 tensor-core flash attention.
// Mechanism-MLP first GEMM fused into the QKV GEMM (N=3584).
// ---------------------------------------------------------------------------

namespace {
constexpr int Bc = 8, Sc = 1024, Dc = 1024, Hc = 16, DFFc = 4096;
constexpr int BS = Bc * Sc;                       // 8192 rows
constexpr size_t NXD = (size_t)BS * Dc;           // 8,388,608
constexpr int NQKV = 3584;                        // q|k|v|mech-hidden

constexpr size_t OFF_X    = 0;
constexpr size_t OFF_H    = OFF_X   + NXD;
constexpr size_t OFF_QKV  = OFF_H   + NXD;                     // BS x 3584
constexpr size_t OFF_CTX  = OFF_QKV + (size_t)BS * NQKV;
constexpr size_t OFF_MECH = OFF_CTX + NXD;                     // BS
constexpr size_t OFF_PE   = OFF_MECH+ (size_t)BS;              // S x D
constexpr size_t OFF_PEP  = OFF_PE  + (size_t)Sc * Dc;         // S x D
constexpr size_t OFF_W5   = OFF_PEP + (size_t)Sc * Dc;         // D x D
constexpr size_t OFF_B5   = OFF_W5  + (size_t)Dc * Dc;         // D
constexpr size_t OFF_WSM  = OFF_B5  + Dc;                      // 8
constexpr size_t OFF_WQKV = OFF_WSM + 8;                       // D x 3584
constexpr size_t OFF_BQKV = OFF_WQKV + (size_t)Dc * NQKV;      // 3584
constexpr size_t OFF_FFH  = OFF_BQKV + NQKV;                   // BS x DFF
constexpr size_t TOTALF   = OFF_FFH + (size_t)BS * DFFc;
}

__device__ float g_buf[TOTALF];

__device__ __forceinline__ float gelu_exact(float v) {
    return 0.5f * v * (1.0f + erff(v * 0.70710678118654752440f));
}

__device__ __forceinline__ float f2tf32(float f) {
    uint32_t r;
    asm("cvt.rna.tf32.f32 %0, %1;" : "=r"(r) : "f"(f));
    return __uint_as_float(r);
}

__device__ __forceinline__ void mma_tf32(float* c, const uint32_t* a, const uint32_t* b) {
    asm volatile(
        "mma.sync.aligned.m16n8k8.row.col.f32.tf32.tf32.f32 "
        "{%0,%1,%2,%3}, {%4,%5,%6,%7}, {%8,%9}, {%0,%1,%2,%3};\n"
        : "+f"(c[0]), "+f"(c[1]), "+f"(c[2]), "+f"(c[3])
        : "r"(a[0]), "r"(a[1]), "r"(a[2]), "r"(a[3]), "r"(b[0]), "r"(b[1]));
}

__device__ __forceinline__ void mma_f16(float* c, const uint32_t* a, uint32_t b0, uint32_t b1) {
    asm volatile(
        "mma.sync.aligned.m16n8k16.row.col.f32.f16.f16.f32 "
        "{%0,%1,%2,%3}, {%4,%5,%6,%7}, {%8,%9}, {%0,%1,%2,%3};\n"
        : "+f"(c[0]), "+f"(c[1]), "+f"(c[2]), "+f"(c[3])
        : "r"(a[0]), "r"(a[1]), "r"(a[2]), "r"(a[3]), "r"(b0), "r"(b1));
}

__device__ __forceinline__ void ldsm_x4(uint32_t& r0, uint32_t& r1, uint32_t& r2, uint32_t& r3,
                                        uint32_t addr) {
    asm volatile("ldmatrix.sync.aligned.m8n8.x4.shared.b16 {%0,%1,%2,%3}, [%4];"
                 : "=r"(r0), "=r"(r1), "=r"(r2), "=r"(r3) : "r"(addr));
}

__device__ __forceinline__ void ldsm_x4t(uint32_t& r0, uint32_t& r1, uint32_t& r2, uint32_t& r3,
                                         uint32_t addr) {
    asm volatile("ldmatrix.sync.aligned.m8n8.x4.trans.shared.b16 {%0,%1,%2,%3}, [%4];"
                 : "=r"(r0), "=r"(r1), "=r"(r2), "=r"(r3) : "r"(addr));
}

__device__ __forceinline__ uint32_t pack_h2(float lo, float hi) {
    __half2 h = __floats2half2_rn(lo, hi);
    return *reinterpret_cast<uint32_t*>(&h);
}

// ---------------------------------------------------------------------------
// fp16 GEMM: C[M,N] = act(A[M,K] @ B[K,N] + bias) + resid   (row-major fp32 io).
// 128x128 block tile, BK=16, 256 threads = 8 warps (4M x 2N), warp tile 32x64.
// A smem [m][16] halfs, 32B rows, chunk swizzle c^((m>>2)&1)  (ldmatrix.x4).
// B smem [k][128] halfs, 256B rows, chunk swizzle c^(k&7)     (ldmatrix.x4.trans).
// act: 0=none, 1=gelu, 2=gelu only for global col >= 3072 (fused mech MLP).
// ---------------------------------------------------------------------------
__global__ void __launch_bounds__(256, 2)
hgemm_k(const float* __restrict__ A, const float* __restrict__ Bm,
        const float* __restrict__ bias, const float* __restrict__ resid,
        float* __restrict__ C, int M, int N, int K, int act)
{
    __shared__ __align__(16) unsigned char smem[4 * 4096];
    // A buffers at 0 / 4096; B buffers at 8192 / 12288 (bytes)
    const uint32_t smem_base = (uint32_t)__cvta_generic_to_shared(smem);

    const int tid = threadIdx.x;
    const int w = tid >> 5, l = tid & 31;
    const int wm = (w & 3) * 32;          // warp M offset
    const int wn = (w >> 2) * 64;         // warp N offset
    const int g = l >> 2, t = l & 3;
    const int bn = blockIdx.x, bm = blockIdx.y;
    const float* Ab = A + (size_t)bm * 128 * K;
    const float* Bb = Bm + (size_t)bn * 128;

    const int arow = tid >> 1;            // 0..127
    const int ac   = tid & 1;             // A chunk (8 halfs)
    const int brow = tid >> 4;            // 0..15
    const int bc   = tid & 15;            // B chunk

    const uint32_t a_st = smem_base + arow * 32 + ((ac ^ ((arow >> 2) & 1)) << 4);
    const uint32_t b_st = smem_base + 8192 + brow * 256 + ((bc ^ (brow & 7)) << 4);

    // fragment load addresses (lane-dependent, fixed across iterations)
    const int amr = ((l >> 3) & 1) * 8 + (l & 7);      // row within 16-tile
    const int acf = l >> 4;                            // chunk 0/1
    const int bkk = ((l >> 4) & 1) * 8 + (l & 7);      // k row
    const int bcb = (wn >> 3) + ((l >> 3) & 1);        // chunk base (+jp*2)

    float acc[2][8][4];
#pragma unroll
    for (int i = 0; i < 2; i++)
#pragma unroll
        for (int j = 0; j < 8; j++)
#pragma unroll
            for (int r = 0; r < 4; r++) acc[i][j][r] = 0.f;

    // ---- prologue: tile 0 -> buffer 0 ----
    {
        const float* Ap = Ab + (size_t)arow * K + ac * 8;
        float4 a0 = *(const float4*)Ap;
        float4 a1 = *(const float4*)(Ap + 4);
        uint4 pa = make_uint4(pack_h2(a0.x, a0.y), pack_h2(a0.z, a0.w),
                              pack_h2(a1.x, a1.y), pack_h2(a1.z, a1.w));
        asm volatile("st.shared.v4.u32 [%0], {%1,%2,%3,%4};" ::
                     "r"(a_st), "r"(pa.x), "r"(pa.y), "r"(pa.z), "r"(pa.w));
        const float* Bp = Bb + (size_t)brow * N + bc * 8;
        float4 b0 = *(const float4*)Bp;
        float4 b1 = *(const float4*)(Bp + 4);
        uint4 pb = make_uint4(pack_h2(b0.x, b0.y), pack_h2(b0.z, b0.w),
                              pack_h2(b1.x, b1.y), pack_h2(b1.z, b1.w));
        asm volatile("st.shared.v4.u32 [%0], {%1,%2,%3,%4};" ::
                     "r"(b_st), "r"(pb.x), "r"(pb.y), "r"(pb.z), "r"(pb.w));
    }
    __syncthreads();

    int cur = 0;
    for (int k0 = 0; k0 < K; k0 += 16) {
        const bool hn = (k0 + 16) < K;
        float4 na0, na1, nb0, nb1;
        if (hn) {
            const float* Ap = Ab + (size_t)arow * K + (k0 + 16) + ac * 8;
            na0 = *(const float4*)Ap;
            na1 = *(const float4*)(Ap + 4);
            const float* Bp = Bb + (size_t)(k0 + 16 + brow) * N + bc * 8;
            nb0 = *(const float4*)Bp;
            nb1 = *(const float4*)(Bp + 4);
        }

        // ---- fragments + MMA from cur buffer ----
        {
            const uint32_t abuf = smem_base + cur * 4096;
            const uint32_t bbuf = smem_base + 8192 + cur * 4096;
            uint32_t af[2][4];
#pragma unroll
            for (int i = 0; i < 2; i++) {
                int m = wm + i * 16 + amr;
                uint32_t ad = abuf + m * 32 + ((acf ^ ((m >> 2) & 1)) << 4);
                ldsm_x4(af[i][0], af[i][1], af[i][2], af[i][3], ad);
            }
#pragma unroll
            for (int jp = 0; jp < 4; jp++) {
                int cB = bcb + jp * 2;
                uint32_t bd = bbuf + bkk * 256 + ((cB ^ (bkk & 7)) << 4);
                uint32_t r0, r1, r2, r3;
                ldsm_x4t(r0, r1, r2, r3, bd);
#pragma unroll
                for (int i = 0; i < 2; i++) {
                    mma_f16(acc[i][jp * 2],     af[i], r0, r2);
                    mma_f16(acc[i][jp * 2 + 1], af[i], r1, r3);
                }
            }
        }

        if (hn) {
            int nxt = cur ^ 1;
            uint4 pa = make_uint4(pack_h2(na0.x, na0.y), pack_h2(na0.z, na0.w),
                                  pack_h2(na1.x, na1.y), pack_h2(na1.z, na1.w));
            asm volatile("st.shared.v4.u32 [%0], {%1,%2,%3,%4};" ::
                         "r"(a_st + nxt * 4096), "r"(pa.x), "r"(pa.y), "r"(pa.z), "r"(pa.w));
            uint4 pb = make_uint4(pack_h2(nb0.x, nb0.y), pack_h2(nb0.z, nb0.w),
                                  pack_h2(nb1.x, nb1.y), pack_h2(nb1.z, nb1.w));
            asm volatile("st.shared.v4.u32 [%0], {%1,%2,%3,%4};" ::
                         "r"(b_st + nxt * 4096), "r"(pb.x), "r"(pb.y), "r"(pb.z), "r"(pb.w));
        }
        __syncthreads();
        cur ^= 1;
    }

    // ---- epilogue ----
#pragma unroll
    for (int i = 0; i < 2; i++) {
        int row0 = bm * 128 + wm + i * 16 + g;
        int row1 = row0 + 8;
        size_t ro0 = (size_t)row0 * N;
        size_t ro1 = (size_t)row1 * N;
#pragma unroll
        for (int j = 0; j < 8; j++) {
            int col = bn * 128 + wn + j * 8 + 2 * t;
            float v0 = acc[i][j][0], v1 = acc[i][j][1];
            float v2 = acc[i][j][2], v3 = acc[i][j][3];
            if (bias) {
                float b0 = bias[col], b1 = bias[col + 1];
                v0 += b0; v1 += b1; v2 += b0; v3 += b1;
            }
            bool dg = (act == 1) || (act == 2 && col >= 3072);
            if (dg) {
                v0 = gelu_exact(v0); v1 = gelu_exact(v1);
                v2 = gelu_exact(v2); v3 = gelu_exact(v3);
            }
            if (resid) {
                v0 += resid[ro0 + col]; v1 += resid[ro0 + col + 1];
                v2 += resid[ro1 + col]; v3 += resid[ro1 + col + 1];
            }
            *(float2*)&C[ro0 + col] = make_float2(v0, v1);
            *(float2*)&C[ro1 + col] = make_float2(v2, v3);
        }
    }
}

// ---------------------------------------------------------------------------
// TF32 flash attention.  QKV packed [BS][3584] (Q|K|V|mech-hidden).
// ---------------------------------------------------------------------------
#define AP 68

__global__ void __launch_bounds__(256)
attn_tc_k(const float* __restrict__ QKV, const float* __restrict__ mech,
          float* __restrict__ Octx)
{
    extern __shared__ float sma[];
    float* Qs = sma;               // [128][AP]
    float* Ks = Qs + 128 * AP;     // [64][AP]  pre-scaled
    float* Vt = Ks + 64 * AP;      // [64][AP]  transposed

    const int tid = threadIdx.x;
    const int w = tid >> 5, l = tid & 31;
    const int g = l >> 2, t = l & 3;
    const int bh = blockIdx.y;
    const int b = bh >> 4, h = bh & 15;
    const int q0 = blockIdx.x * 128;
    const int qr = w * 16;

    {
        int r = tid >> 2;
        int c = (tid & 3) * 16;
#pragma unroll
        for (int half = 0; half < 2; half++) {
            int rr = r + half * 64;
            const float* qp = QKV + ((size_t)b * 1024 + q0 + rr) * NQKV + h * 64 + c;
#pragma unroll
            for (int u = 0; u < 4; u++) {
                float4 v = *(const float4*)(qp + u * 4);
                float4 cv = make_float4(f2tf32(v.x), f2tf32(v.y), f2tf32(v.z), f2tf32(v.w));
                *(float4*)&Qs[rr * AP + c + u * 4] = cv;
            }
        }
    }

    float m0 = -1e30f, m1 = -1e30f, l0 = 0.f, l1 = 0.f;
    float acc[8][4];
#pragma unroll
    for (int e = 0; e < 8; e++)
#pragma unroll
        for (int r = 0; r < 4; r++) acc[e][r] = 0.f;
    __syncthreads();

    for (int kt = 0; kt < 16; kt++) {
        const int k0 = kt * 64;
        {
            int r = tid >> 2;
            int c = (tid & 3) * 16;
            size_t rowb = ((size_t)b * 1024 + k0 + r) * NQKV + h * 64;
            float fac = 0.125f * (1.f + mech[(size_t)b * 1024 + k0 + r]);
            const float* kp = QKV + rowb + 1024 + c;
            const float* vp = QKV + rowb + 2048 + c;
#pragma unroll
            for (int u = 0; u < 4; u++) {
                float4 kv = *(const float4*)(kp + u * 4);
                float4 ck = make_float4(f2tf32(kv.x * fac), f2tf32(kv.y * fac),
                                        f2tf32(kv.z * fac), f2tf32(kv.w * fac));
                *(float4*)&Ks[r * AP + c + u * 4] = ck;
                float4 vv = *(const float4*)(vp + u * 4);
                Vt[(c + u * 4 + 0) * AP + r] = f2tf32(vv.x);
                Vt[(c + u * 4 + 1) * AP + r] = f2tf32(vv.y);
                Vt[(c + u * 4 + 2) * AP + r] = f2tf32(vv.z);
                Vt[(c + u * 4 + 3) * AP + r] = f2tf32(vv.w);
            }
        }
        __syncthreads();

        float s[8][4];
#pragma unroll
        for (int j = 0; j < 8; j++)
#pragma unroll
            for (int r = 0; r < 4; r++) s[j][r] = 0.f;
#pragma unroll
        for (int kd = 0; kd < 8; kd++) {
            uint32_t a[4];
            const float* p0 = &Qs[(qr + g) * AP + kd * 8 + t];
            const float* p1 = &Qs[(qr + 8 + g) * AP + kd * 8 + t];
            a[0] = __float_as_uint(p0[0]);
            a[1] = __float_as_uint(p1[0]);
            a[2] = __float_as_uint(p0[4]);
            a[3] = __float_as_uint(p1[4]);
#pragma unroll
            for (int j = 0; j < 8; j++) {
                uint32_t bb[2];
                bb[0] = __float_as_uint(Ks[(j * 8 + g) * AP + kd * 8 + t]);
                bb[1] = __float_as_uint(Ks[(j * 8 + g) * AP + kd * 8 + t + 4]);
                mma_tf32(s[j], a, bb);
            }
        }

        float mx0 = -1e30f, mx1 = -1e30f;
#pragma unroll
        for (int j = 0; j < 8; j++) {
            mx0 = fmaxf(mx0, fmaxf(s[j][0], s[j][1]));
            mx1 = fmaxf(mx1, fmaxf(s[j][2], s[j][3]));
        }
        mx0 = fmaxf(mx0, __shfl_xor_sync(0xffffffffu, mx0, 1));
        mx0 = fmaxf(mx0, __shfl_xor_sync(0xffffffffu, mx0, 2));
        mx1 = fmaxf(mx1, __shfl_xor_sync(0xffffffffu, mx1, 1));
        mx1 = fmaxf(mx1, __shfl_xor_sync(0xffffffffu, mx1, 2));
        float mn0 = fmaxf(m0, mx0), mn1 = fmaxf(m1, mx1);
        float al0 = __expf(m0 - mn0), al1 = __expf(m1 - mn1);
        float sum0 = 0.f, sum1 = 0.f;
#pragma unroll
        for (int j = 0; j < 8; j++) {
            s[j][0] = __expf(s[j][0] - mn0);
            s[j][1] = __expf(s[j][1] - mn0);
            s[j][2] = __expf(s[j][2] - mn1);
            s[j][3] = __expf(s[j][3] - mn1);
            sum0 += s[j][0] + s[j][1];
            sum1 += s[j][2] + s[j][3];
        }
        sum0 += __shfl_xor_sync(0xffffffffu, sum0, 1);
        sum0 += __shfl_xor_sync(0xffffffffu, sum0, 2);
        sum1 += __shfl_xor_sync(0xffffffffu, sum1, 1);
        sum1 += __shfl_xor_sync(0xffffffffu, sum1, 2);
        l0 = l0 * al0 + sum0;
        l1 = l1 * al1 + sum1;
        m0 = mn0; m1 = mn1;
#pragma unroll
        for (int e = 0; e < 8; e++) {
            acc[e][0] *= al0; acc[e][1] *= al0;
            acc[e][2] *= al1; acc[e][3] *= al1;
        }

        const int s0l = (l & 28) | (t >> 1);
        const int s1l = s0l + 2;
        const bool sel = (t & 1);
#pragma unroll
        for (int j = 0; j < 8; j++) {
            uint32_t p0 = __float_as_uint(f2tf32(s[j][0]));
            uint32_t p1 = __float_as_uint(f2tf32(s[j][1]));
            uint32_t p2 = __float_as_uint(f2tf32(s[j][2]));
            uint32_t p3 = __float_as_uint(f2tf32(s[j][3]));
            uint32_t x0 = __shfl_sync(0xffffffffu, p0, s0l);
            uint32_t x1 = __shfl_sync(0xffffffffu, p1, s0l);
            uint32_t x2 = __shfl_sync(0xffffffffu, p2, s0l);
            uint32_t x3 = __shfl_sync(0xffffffffu, p3, s0l);
            uint32_t y0 = __shfl_sync(0xffffffffu, p0, s1l);
            uint32_t y1 = __shfl_sync(0xffffffffu, p1, s1l);
            uint32_t y2 = __shfl_sync(0xffffffffu, p2, s1l);
            uint32_t y3 = __shfl_sync(0xffffffffu, p3, s1l);
            uint32_t a[4];
            a[0] = sel ? x1 : x0;
            a[1] = sel ? x3 : x2;
            a[2] = sel ? y1 : y0;
            a[3] = sel ? y3 : y2;
#pragma unroll
            for (int e = 0; e < 8; e++) {
                uint32_t bb[2];
                bb[0] = __float_as_uint(Vt[(e * 8 + g) * AP + j * 8 + t]);
                bb[1] = __float_as_uint(Vt[(e * 8 + g) * AP + j * 8 + t + 4]);
                mma_tf32(acc[e], a, bb);
            }
        }
        __syncthreads();
    }

    float inv0 = 1.f / l0, inv1 = 1.f / l1;
    size_t o0 = ((size_t)b * 1024 + q0 + qr + g) * 1024 + h * 64;
    size_t o1 = o0 + (size_t)8 * 1024;
#pragma unroll
    for (int e = 0; e < 8; e++) {
        *(float2*)&Octx[o0 + e * 8 + 2 * t] = make_float2(acc[e][0] * inv0, acc[e][1] * inv0);
        *(float2*)&Octx[o1 + e * 8 + 2 * t] = make_float2(acc[e][2] * inv1, acc[e][3] * inv1);
    }
}

// ---------------------------------------------------------------------------
// LayerNorm over last dim (1024). One block (256 threads) per row.
// ---------------------------------------------------------------------------
__global__ void layernorm_k(const float* __restrict__ x, const float* __restrict__ g,
                            const float* __restrict__ b, float* __restrict__ o)
{
    int row = blockIdx.x;
    const float4* xr = (const float4*)(x + (size_t)row * 1024);
    float4 v = xr[threadIdx.x];
    float s  = v.x + v.y + v.z + v.w;
    float ss = fmaf(v.x, v.x, fmaf(v.y, v.y, fmaf(v.z, v.z, v.w * v.w)));
#pragma unroll
    for (int off = 16; off > 0; off >>= 1) {
        s  += __shfl_xor_sync(0xffffffffu, s,  off);
        ss += __shfl_xor_sync(0xffffffffu, ss, off);
    }
    __shared__ float ws[8], wss[8];
    __shared__ float s_mean, s_inv;
    int w = threadIdx.x >> 5, ln = threadIdx.x & 31;
    if (ln == 0) { ws[w] = s; wss[w] = ss; }
    __syncthreads();
    if (threadIdx.x == 0) {
        float S = 0.f, SS = 0.f;
#pragma unroll
        for (int i = 0; i < 8; i++) { S += ws[i]; SS += wss[i]; }
        float mean = S * (1.f / 1024.f);
        float var  = SS * (1.f / 1024.f) - mean * mean;
        s_mean = mean;
        s_inv  = rsqrtf(var + 1e-5f);
    }
    __syncthreads();
    float mean = s_mean, inv = s_inv;
    float4 gv = ((const float4*)g)[threadIdx.x];
    float4 bv = ((const float4*)b)[threadIdx.x];
    float4 r;
    r.x = (v.x - mean) * inv * gv.x + bv.x;
    r.y = (v.y - mean) * inv * gv.y + bv.y;
    r.z = (v.z - mean) * inv * gv.z + bv.z;
    r.w = (v.w - mean) * inv * gv.w + bv.w;
    ((float4*)(o + (size_t)row * 1024))[threadIdx.x] = r;
}

// ---------------------------------------------------------------------------
// Small elementwise kernels
// ---------------------------------------------------------------------------
__global__ void build_pe_k(const float* __restrict__ pos, const float* __restrict__ tim,
                           float* __restrict__ pe)
{
    int i = blockIdx.x * blockDim.x + threadIdx.x;   // S*D = 1M
    int s = i >> 10, d = i & 1023;
    pe[i] = (d < 512) ? pos[s * 512 + d] : tim[s * 512 + (d - 512)];
}

__global__ void add_pe_k(const float* __restrict__ xin, const float* __restrict__ pep,
                         float* __restrict__ x)
{
    size_t i = (size_t)blockIdx.x * blockDim.x + threadIdx.x;  // B*S*D
    x[i] = xin[i] + pep[i & ((size_t)(1 << 20) - 1)];
}

__global__ void softmax5_k(const float* __restrict__ elw, float* __restrict__ wsm,
                           float* __restrict__ out_w)
{
    if (threadIdx.x == 0) {
        float m = elw[0];
        for (int p = 1; p < 5; p++) m = fmaxf(m, elw[p]);
        float e[5], s = 0.f;
        for (int p = 0; p < 5; p++) { e[p] = expf(elw[p] - m); s += e[p]; }
        float inv = 1.f / s;
        for (int p = 0; p < 5; p++) { wsm[p] = e[p] * inv; out_w[p] = e[p] * inv; }
    }
}

__global__ void combine_w5_k(const float* __restrict__ ew, const float* __restrict__ wsm,
                             float* __restrict__ w5)
{
    int i = blockIdx.x * blockDim.x + threadIdx.x;   // D*D
    float w0 = wsm[0], w1 = wsm[1], w2 = wsm[2], w3 = wsm[3], w4 = wsm[4];
    const size_t DD = (size_t)1024 * 1024;
    float v = w0 * ew[i] + w1 * ew[DD + i] + w2 * ew[2 * DD + i]
            + w3 * ew[3 * DD + i] + w4 * ew[4 * DD + i];
    w5[i] = v;
}

__global__ void combine_b5_k(const float* __restrict__ eb, const float* __restrict__ wsm,
                             float* __restrict__ b5)
{
    int i = blockIdx.x * blockDim.x + threadIdx.x;   // D
    float v = 0.f;
    for (int p = 0; p < 5; p++) v += wsm[p] * eb[p * 1024 + i];
    b5[i] = v;
}

// Pack qw|kw|vw|mw1 -> [D][3584], biases -> [3584]
__global__ void pack_qkvm_k(const float* __restrict__ qw, const float* __restrict__ kw,
                            const float* __restrict__ vw, const float* __restrict__ mw1,
                            const float* __restrict__ qb, const float* __restrict__ kb,
                            const float* __restrict__ vb, const float* __restrict__ mb1,
                            float* __restrict__ wq, float* __restrict__ bq)
{
    int i = blockIdx.x * blockDim.x + threadIdx.x;   // D * 3584
    int k = i / NQKV, n = i - k * NQKV;
    float v;
    if (n < 1024)      v = qw[k * 1024 + n];
    else if (n < 2048) v = kw[k * 1024 + n - 1024];
    else if (n < 3072) v = vw[k * 1024 + n - 2048];
    else               v = mw1[k * 512 + n - 3072];
    wq[i] = v;
    if (i < NQKV) {
        float b;
        if (i < 1024)      b = qb[i];
        else if (i < 2048) b = kb[i - 1024];
        else if (i < 3072) b = vb[i - 2048];
        else               b = mb1[i - 3072];
        bq[i] = b;
    }
}

// mech[r] = sigmoid(dot(qkv[r, 3072:3584], mw2) + mb2); one warp per row.
__global__ void mech_out_k(const float* __restrict__ qkv, const float* __restrict__ mw2,
                           const float* __restrict__ mb2, float* __restrict__ mech,
                           float* __restrict__ out_mech)
{
    int row  = blockIdx.x * 8 + (threadIdx.x >> 5);
    int lane = threadIdx.x & 31;
    const float* r = qkv + (size_t)row * NQKV + 3072;
    float s = 0.f;
#pragma unroll
    for (int c = lane; c < 512; c += 32) s = fmaf(r[c], mw2[c], s);
#pragma unroll
    for (int off = 16; off > 0; off >>= 1) s += __shfl_xor_sync(0xffffffffu, s, off);
    if (lane == 0) {
        float t = s + mb2[0];
        float m = 1.f / (1.f + expf(-t));
        mech[row] = m;
        out_mech[row] = m;
    }
}

// ---------------------------------------------------------------------------
// Host launcher
// ---------------------------------------------------------------------------
extern "C" void kernel_launch(void* const* d_in, const int* in_sizes, int n_in,
                              void* d_out, int out_size)
{
    (void)in_sizes; (void)n_in; (void)out_size;
    const float* x_in = (const float*)d_in[0];
    const float* pos  = (const float*)d_in[1];
    const float* tim  = (const float*)d_in[2];
    const float* wi   = (const float*)d_in[3];
    const float* bi   = (const float*)d_in[4];
    const float* g1   = (const float*)d_in[5];
    const float* be1  = (const float*)d_in[6];
    const float* g2   = (const float*)d_in[7];
    const float* be2  = (const float*)d_in[8];
    const float* g3   = (const float*)d_in[9];
    const float* be3  = (const float*)d_in[10];
    const float* qw   = (const float*)d_in[11];
    const float* qb   = (const float*)d_in[12];
    const float* kw   = (const float*)d_in[13];
    const float* kb   = (const float*)d_in[14];
    const float* vw   = (const float*)d_in[15];
    const float* vb   = (const float*)d_in[16];
    const float* ow   = (const float*)d_in[17];
    const float* ob   = (const float*)d_in[18];
    const float* mw1  = (const float*)d_in[19];
    const float* mb1  = (const float*)d_in[20];
    const float* mw2  = (const float*)d_in[21];
    const float* mb2  = (const float*)d_in[22];
    const float* ew   = (const float*)d_in[23];
    const float* eb   = (const float*)d_in[24];
    const float* elw  = (const float*)d_in[25];
    const float* fw1  = (const float*)d_in[26];
    const float* fb1  = (const float*)d_in[27];
    const float* fw2  = (const float*)d_in[28];
    const float* fb2  = (const float*)d_in[29];

    float* out = (float*)d_out;
    float* out_mech = out + NXD;          // 8,388,608
    float* out_w    = out + NXD + BS;     // +8192

    float* base = nullptr;
    cudaGetSymbolAddress((void**)&base, g_buf);
    float* gx    = base + OFF_X;
    float* gh    = base + OFF_H;
    float* gqkv  = base + OFF_QKV;
    float* gctx  = base + OFF_CTX;
    float* gmech = base + OFF_MECH;
    float* gpe   = base + OFF_PE;
    float* gpep  = base + OFF_PEP;
    float* gw5   = base + OFF_W5;
    float* gb5   = base + OFF_B5;
    float* gwsm  = base + OFF_WSM;
    float* gwqkv = base + OFF_WQKV;
    float* gbqkv = base + OFF_BQKV;
    float* gffh  = base + OFF_FFH;

    const int ATTN_SMEM = 256 * AP * (int)sizeof(float);   // 69632 B
    cudaFuncSetAttribute(attn_tc_k, cudaFuncAttributeMaxDynamicSharedMemorySize, ATTN_SMEM);

    // 1) positional/timing embedding
    build_pe_k<<<(Sc * Dc) / 256, 256>>>(pos, tim, gpe);
    hgemm_k<<<dim3(Dc / 128, Sc / 128), 256>>>(gpe, wi, bi, nullptr, gpep, Sc, Dc, Dc, 0);
    add_pe_k<<<(unsigned)(NXD / 256), 256>>>(x_in, gpep, gx);

    // 2) norm1 -> h
    layernorm_k<<<BS, 256>>>(gx, g1, be1, gh);

    // 3) fused QKV + mech-hidden projection (N=3584; gelu on cols >= 3072)
    pack_qkvm_k<<<(Dc * NQKV) / 256, 256>>>(qw, kw, vw, mw1, qb, kb, vb, mb1, gwqkv, gbqkv);
    hgemm_k<<<dim3(NQKV / 128, BS / 128), 256>>>(gh, gwqkv, gbqkv, nullptr, gqkv, BS, NQKV, Dc, 2);

    // 4) mechanism output
    mech_out_k<<<BS / 8, 256>>>(gqkv, mw2, mb2, gmech, out_mech);

    // 5) flash attention (tensor cores; mech folded into K)
    attn_tc_k<<<dim3(Sc / 128, Bc * Hc), 256, ATTN_SMEM>>>(gqkv, gmech, gctx);

    // 6) output projection + residual
    hgemm_k<<<dim3(Dc / 128, BS / 128), 256>>>(gctx, ow, ob, gx, gx, BS, Dc, Dc, 0);

    // 7) five elements (folded to one GEMM)
    layernorm_k<<<BS, 256>>>(gx, g2, be2, gh);
    softmax5_k<<<1, 32>>>(elw, gwsm, out_w);
    combine_w5_k<<<(Dc * Dc) / 256, 256>>>(ew, gwsm, gw5);
    combine_b5_k<<<Dc / 256, 256>>>(eb, gwsm, gb5);
    hgemm_k<<<dim3(Dc / 128, BS / 128), 256>>>(gh, gw5, gb5, gx, gx, BS, Dc, Dc, 0);

    // 8) FFN
    layernorm_k<<<BS, 256>>>(gx, g3, be3, gh);
    hgemm_k<<<dim3(DFFc / 128, BS / 128), 256>>>(gh, fw1, fb1, nullptr, gffh, BS, DFFc, Dc, 1);
    hgemm_k<<<dim3(Dc / 128, BS / 128), 256>>>(gffh, fw2, fb2, gx, out, BS, Dc, DFFc, 0);
}

// round 7
// speedup vs baseline: 5.2646x; 1.2571x over previous
#include <cuda_runtime.h>
#include <cuda_fp16.h>
#include <math.h>
#include <stdint.h>

// ---------------------------------------------------------------------------
// MechanismTransformerBlock  B=8 S=1024 D=1024 H=16 DH=64 DFF=4096
// End-to-end fp16 tensor-core data path:
//  - hgemm: fp16 operands in gmem, ldmatrix + mma.m16n8k16, fp32 accum
//  - fp16 flash attention (P pairs pack straight into A-frags, no shuffles)
//  - LN writes fp16; GEMM->GEMM intermediates stored fp16
// ---------------------------------------------------------------------------

namespace {
constexpr int Bc = 8, Sc = 1024, Dc = 1024, Hc = 16, DFFc = 4096;
constexpr int BS = Bc * Sc;                       // 8192 rows
constexpr size_t NXD = (size_t)BS * Dc;           // 8,388,608
constexpr int NQKV = 3584;                        // q|k|v|mech-hidden

// fp32 scratch
constexpr size_t OFF_X    = 0;
constexpr size_t OFF_PEP  = OFF_X   + NXD;                    // S x D
constexpr size_t OFF_MECH = OFF_PEP + (size_t)Sc * Dc;        // BS
constexpr size_t OFF_B5   = OFF_MECH+ (size_t)BS;             // D
constexpr size_t OFF_WSM  = OFF_B5  + Dc;                     // 8
constexpr size_t OFF_BQKV = OFF_WSM + 8;                      // 3584
constexpr size_t TOTALF   = OFF_BQKV + NQKV;

// fp16 weight staging offsets (in halfs)
constexpr size_t W16_WI  = 0;                                  // 1M
constexpr size_t W16_OW  = W16_WI  + (size_t)Dc * Dc;
constexpr size_t W16_W5  = W16_OW  + (size_t)Dc * Dc;
constexpr size_t W16_FW1 = W16_W5  + (size_t)Dc * Dc;          // 4M
constexpr size_t W16_FW2 = W16_FW1 + (size_t)Dc * DFFc;        // 4M
constexpr size_t W16_QKV = W16_FW2 + (size_t)DFFc * Dc;        // 3.67M
constexpr size_t W16_TOT = W16_QKV + (size_t)Dc * NQKV;
}

__device__ float  g_buf[TOTALF];
__device__ __half g_h16[NXD];                 // LN output
__device__ __half g_qkv16[(size_t)BS * NQKV]; // q|k|v|mech-hidden
__device__ __half g_ctx16[NXD];               // attention output
__device__ __half g_ffh16[(size_t)BS * DFFc]; // FFN hidden
__device__ __half g_pe16[(size_t)Sc * Dc];
__device__ __half g_w16[W16_TOT];

__device__ __forceinline__ float gelu_exact(float v) {
    return 0.5f * v * (1.0f + erff(v * 0.70710678118654752440f));
}

__device__ __forceinline__ void mma_f16(float* c, const uint32_t* a, uint32_t b0, uint32_t b1) {
    asm volatile(
        "mma.sync.aligned.m16n8k16.row.col.f32.f16.f16.f32 "
        "{%0,%1,%2,%3}, {%4,%5,%6,%7}, {%8,%9}, {%0,%1,%2,%3};\n"
        : "+f"(c[0]), "+f"(c[1]), "+f"(c[2]), "+f"(c[3])
        : "r"(a[0]), "r"(a[1]), "r"(a[2]), "r"(a[3]), "r"(b0), "r"(b1));
}

__device__ __forceinline__ void ldsm_x4(uint32_t& r0, uint32_t& r1, uint32_t& r2, uint32_t& r3,
                                        uint32_t addr) {
    asm volatile("ldmatrix.sync.aligned.m8n8.x4.shared.b16 {%0,%1,%2,%3}, [%4];"
                 : "=r"(r0), "=r"(r1), "=r"(r2), "=r"(r3) : "r"(addr));
}

__device__ __forceinline__ void ldsm_x4t(uint32_t& r0, uint32_t& r1, uint32_t& r2, uint32_t& r3,
                                         uint32_t addr) {
    asm volatile("ldmatrix.sync.aligned.m8n8.x4.trans.shared.b16 {%0,%1,%2,%3}, [%4];"
                 : "=r"(r0), "=r"(r1), "=r"(r2), "=r"(r3) : "r"(addr));
}

__device__ __forceinline__ uint32_t h2bits(float lo, float hi) {
    __half2 h = __floats2half2_rn(lo, hi);
    return *reinterpret_cast<uint32_t*>(&h);
}

// ---------------------------------------------------------------------------
// fp16 GEMM: C = act(A @ B + bias) + resid.  A,B fp16 gmem; C fp32 or fp16.
// 128x128 tile, BK=16, 256 thr = 8 warps (4M x 2N), warp tile 32x64,
// double-buffered smem. act: 0 none, 1 gelu, 2 gelu iff global col >= 3072.
// ---------------------------------------------------------------------------
__global__ void __launch_bounds__(256, 2)
hgemm_k(const __half* __restrict__ A, const __half* __restrict__ Bm,
        const float* __restrict__ bias, const float* __restrict__ resid,
        void* __restrict__ Cv, int M, int N, int K, int act, int outh)
{
    __shared__ __align__(16) unsigned char smem[4 * 4096];
    const uint32_t smem_base = (uint32_t)__cvta_generic_to_shared(smem);

    const int tid = threadIdx.x;
    const int w = tid >> 5, l = tid & 31;
    const int wm = (w & 3) * 32;
    const int wn = (w >> 2) * 64;
    const int g = l >> 2, t = l & 3;
    const int bn = blockIdx.x, bm = blockIdx.y;
    const __half* Ab = A + (size_t)bm * 128 * K;
    const __half* Bb = Bm + (size_t)bn * 128;

    const int arow = tid >> 1;            // 0..127
    const int ac   = tid & 1;
    const int brow = tid >> 4;            // 0..15
    const int bc   = tid & 15;

    const uint32_t a_st = smem_base + arow * 32 + ((ac ^ ((arow >> 2) & 1)) << 4);
    const uint32_t b_st = smem_base + 8192 + brow * 256 + ((bc ^ (brow & 7)) << 4);

    const int amr = ((l >> 3) & 1) * 8 + (l & 7);
    const int acf = l >> 4;
    const int bkk = ((l >> 4) & 1) * 8 + (l & 7);
    const int bcb = (wn >> 3) + ((l >> 3) & 1);

    float acc[2][8][4];
#pragma unroll
    for (int i = 0; i < 2; i++)
#pragma unroll
        for (int j = 0; j < 8; j++)
#pragma unroll
            for (int r = 0; r < 4; r++) acc[i][j][r] = 0.f;

    {
        uint4 pa = *(const uint4*)(Ab + (size_t)arow * K + ac * 8);
        asm volatile("st.shared.v4.u32 [%0], {%1,%2,%3,%4};" ::
                     "r"(a_st), "r"(pa.x), "r"(pa.y), "r"(pa.z), "r"(pa.w));
        uint4 pb = *(const uint4*)(Bb + (size_t)brow * N + bc * 8);
        asm volatile("st.shared.v4.u32 [%0], {%1,%2,%3,%4};" ::
                     "r"(b_st), "r"(pb.x), "r"(pb.y), "r"(pb.z), "r"(pb.w));
    }
    __syncthreads();

    int cur = 0;
    for (int k0 = 0; k0 < K; k0 += 16) {
        const bool hn = (k0 + 16) < K;
        uint4 pa, pb;
        if (hn) {
            pa = *(const uint4*)(Ab + (size_t)arow * K + (k0 + 16) + ac * 8);
            pb = *(const uint4*)(Bb + (size_t)(k0 + 16 + brow) * N + bc * 8);
        }
        {
            const uint32_t abuf = smem_base + cur * 4096;
            const uint32_t bbuf = smem_base + 8192 + cur * 4096;
            uint32_t af[2][4];
#pragma unroll
            for (int i = 0; i < 2; i++) {
                int m = wm + i * 16 + amr;
                uint32_t ad = abuf + m * 32 + ((acf ^ ((m >> 2) & 1)) << 4);
                ldsm_x4(af[i][0], af[i][1], af[i][2], af[i][3], ad);
            }
#pragma unroll
            for (int jp = 0; jp < 4; jp++) {
                int cB = bcb + jp * 2;
                uint32_t bd = bbuf + bkk * 256 + ((cB ^ (bkk & 7)) << 4);
                uint32_t r0, r1, r2, r3;
                ldsm_x4t(r0, r1, r2, r3, bd);
#pragma unroll
                for (int i = 0; i < 2; i++) {
                    mma_f16(acc[i][jp * 2],     af[i], r0, r2);
                    mma_f16(acc[i][jp * 2 + 1], af[i], r1, r3);
                }
            }
        }
        if (hn) {
            int nxt = cur ^ 1;
            asm volatile("st.shared.v4.u32 [%0], {%1,%2,%3,%4};" ::
                         "r"(a_st + nxt * 4096), "r"(pa.x), "r"(pa.y), "r"(pa.z), "r"(pa.w));
            asm volatile("st.shared.v4.u32 [%0], {%1,%2,%3,%4};" ::
                         "r"(b_st + nxt * 4096), "r"(pb.x), "r"(pb.y), "r"(pb.z), "r"(pb.w));
        }
        __syncthreads();
        cur ^= 1;
    }

#pragma unroll
    for (int i = 0; i < 2; i++) {
        int row0 = bm * 128 + wm + i * 16 + g;
        int row1 = row0 + 8;
        size_t ro0 = (size_t)row0 * N;
        size_t ro1 = (size_t)row1 * N;
#pragma unroll
        for (int j = 0; j < 8; j++) {
            int col = bn * 128 + wn + j * 8 + 2 * t;
            float v0 = acc[i][j][0], v1 = acc[i][j][1];
            float v2 = acc[i][j][2], v3 = acc[i][j][3];
            if (bias) {
                float b0 = bias[col], b1 = bias[col + 1];
                v0 += b0; v1 += b1; v2 += b0; v3 += b1;
            }
            bool dg = (act == 1) || (act == 2 && col >= 3072);
            if (dg) {
                v0 = gelu_exact(v0); v1 = gelu_exact(v1);
                v2 = gelu_exact(v2); v3 = gelu_exact(v3);
            }
            if (resid) {
                v0 += resid[ro0 + col]; v1 += resid[ro0 + col + 1];
                v2 += resid[ro1 + col]; v3 += resid[ro1 + col + 1];
            }
            if (outh) {
                __half* C = (__half*)Cv;
                *(uint32_t*)&C[ro0 + col] = h2bits(v0, v1);
                *(uint32_t*)&C[ro1 + col] = h2bits(v2, v3);
            } else {
                float* C = (float*)Cv;
                *(float2*)&C[ro0 + col] = make_float2(v0, v1);
                *(float2*)&C[ro1 + col] = make_float2(v2, v3);
            }
        }
    }
}

// ---------------------------------------------------------------------------
// fp16 flash attention.  QKV fp16 [BS][3584]; mech factor folded into K.
// Block: one (b,h), Q tile 128; K/V tiles 64 keys. 8 warps, warp owns 16 rows.
// Smem: Q[128][64], K[64][64], V[64][64] fp16, rows 128B,
// swizzle chunk c ^ ((r + (r>>3)) & 7).
// ---------------------------------------------------------------------------
__device__ __forceinline__ uint32_t aswz(int r, int c) {
    return (uint32_t)(r * 128 + ((c ^ ((r + (r >> 3)) & 7)) << 4));
}

__global__ void __launch_bounds__(256)
attn_h_k(const __half* __restrict__ QKV, const float* __restrict__ mech,
         __half* __restrict__ Octx)
{
    __shared__ __align__(16) __half smem[16384];   // Q 16KB | K 8KB | V 8KB
    const uint32_t sb = (uint32_t)__cvta_generic_to_shared(smem);
    const uint32_t kb = sb + 16384;
    const uint32_t vb = sb + 24576;

    const int tid = threadIdx.x;
    const int w = tid >> 5, l = tid & 31;
    const int g = l >> 2, t = l & 3;
    const int bh = blockIdx.y;
    const int b = bh >> 4, h = bh & 15;
    const int q0 = blockIdx.x * 128;
    const int qr = w * 16;

    // ---- load Q tile ----
    {
        int r = tid >> 1;
        int c0 = (tid & 1) * 4;
        const __half* qp = QKV + ((size_t)(b * 1024 + q0 + r)) * NQKV + h * 64;
#pragma unroll
        for (int u = 0; u < 4; u++) {
            int c = c0 + u;
            uint4 v = *(const uint4*)(qp + c * 8);
            asm volatile("st.shared.v4.u32 [%0], {%1,%2,%3,%4};" ::
                         "r"(sb + aswz(r, c)), "r"(v.x), "r"(v.y), "r"(v.z), "r"(v.w));
        }
    }

    float m0 = -1e30f, m1 = -1e30f, l0 = 0.f, l1 = 0.f;
    float acc[8][4];
#pragma unroll
    for (int e = 0; e < 8; e++)
#pragma unroll
        for (int r = 0; r < 4; r++) acc[e][r] = 0.f;
    __syncthreads();

    for (int kt = 0; kt < 16; kt++) {
        const int k0 = kt * 64;
        // ---- load K (scaled) and V ----
        {
            int r = tid >> 2;
            int c0 = (tid & 3) * 2;
            size_t rowb = ((size_t)(b * 1024 + k0 + r)) * NQKV + h * 64;
            float f = 0.125f * (1.f + mech[(size_t)b * 1024 + k0 + r]);
            __half2 fh = __float2half2_rn(f);
            const __half* kp = QKV + rowb + 1024;
            const __half* vp = QKV + rowb + 2048;
#pragma unroll
            for (int u = 0; u < 2; u++) {
                int c = c0 + u;
                uint4 kv = *(const uint4*)(kp + c * 8);
                __half2* kh = (__half2*)&kv;
                kh[0] = __hmul2(kh[0], fh);
                kh[1] = __hmul2(kh[1], fh);
                kh[2] = __hmul2(kh[2], fh);
                kh[3] = __hmul2(kh[3], fh);
                asm volatile("st.shared.v4.u32 [%0], {%1,%2,%3,%4};" ::
                             "r"(kb + aswz(r, c)), "r"(kv.x), "r"(kv.y), "r"(kv.z), "r"(kv.w));
                uint4 vv = *(const uint4*)(vp + c * 8);
                asm volatile("st.shared.v4.u32 [%0], {%1,%2,%3,%4};" ::
                             "r"(vb + aswz(r, c)), "r"(vv.x), "r"(vv.y), "r"(vv.z), "r"(vv.w));
            }
        }
        __syncthreads();

        // ---- S = Q K'^T ----
        float s[8][4];
#pragma unroll
        for (int j = 0; j < 8; j++)
#pragma unroll
            for (int r = 0; r < 4; r++) s[j][r] = 0.f;
#pragma unroll
        for (int kc = 0; kc < 4; kc++) {
            uint32_t a[4];
            {
                int row = qr + (l & 7) + ((l >> 3) & 1) * 8;
                int chunk = 2 * kc + (l >> 4);
                ldsm_x4(a[0], a[1], a[2], a[3], sb + aswz(row, chunk));
            }
#pragma unroll
            for (int jp = 0; jp < 4; jp++) {
                int key = jp * 16 + ((l >> 4) & 1) * 8 + (l & 7);
                int chunk = 2 * kc + ((l >> 3) & 1);
                uint32_t r0, r1, r2, r3;
                ldsm_x4(r0, r1, r2, r3, kb + aswz(key, chunk));
                mma_f16(s[jp * 2],     a, r0, r1);
                mma_f16(s[jp * 2 + 1], a, r2, r3);
            }
        }

        // ---- online softmax (registers + quad shuffles) ----
        float mx0 = -1e30f, mx1 = -1e30f;
#pragma unroll
        for (int j = 0; j < 8; j++) {
            mx0 = fmaxf(mx0, fmaxf(s[j][0], s[j][1]));
            mx1 = fmaxf(mx1, fmaxf(s[j][2], s[j][3]));
        }
        mx0 = fmaxf(mx0, __shfl_xor_sync(0xffffffffu, mx0, 1));
        mx0 = fmaxf(mx0, __shfl_xor_sync(0xffffffffu, mx0, 2));
        mx1 = fmaxf(mx1, __shfl_xor_sync(0xffffffffu, mx1, 1));
        mx1 = fmaxf(mx1, __shfl_xor_sync(0xffffffffu, mx1, 2));
        float mn0 = fmaxf(m0, mx0), mn1 = fmaxf(m1, mx1);
        float al0 = __expf(m0 - mn0), al1 = __expf(m1 - mn1);
        float sum0 = 0.f, sum1 = 0.f;
#pragma unroll
        for (int j = 0; j < 8; j++) {
            s[j][0] = __expf(s[j][0] - mn0);
            s[j][1] = __expf(s[j][1] - mn0);
            s[j][2] = __expf(s[j][2] - mn1);
            s[j][3] = __expf(s[j][3] - mn1);
            sum0 += s[j][0] + s[j][1];
            sum1 += s[j][2] + s[j][3];
        }
        sum0 += __shfl_xor_sync(0xffffffffu, sum0, 1);
        sum0 += __shfl_xor_sync(0xffffffffu, sum0, 2);
        sum1 += __shfl_xor_sync(0xffffffffu, sum1, 1);
        sum1 += __shfl_xor_sync(0xffffffffu, sum1, 2);
        l0 = l0 * al0 + sum0;
        l1 = l1 * al1 + sum1;
        m0 = mn0; m1 = mn1;
#pragma unroll
        for (int e = 0; e < 8; e++) {
            acc[e][0] *= al0; acc[e][1] *= al0;
            acc[e][2] *= al1; acc[e][3] *= al1;
        }

        // ---- acc += P V : P packs straight into A-frags ----
#pragma unroll
        for (int u = 0; u < 4; u++) {
            uint32_t a[4];
            a[0] = h2bits(s[2 * u][0],     s[2 * u][1]);
            a[1] = h2bits(s[2 * u][2],     s[2 * u][3]);
            a[2] = h2bits(s[2 * u + 1][0], s[2 * u + 1][1]);
            a[3] = h2bits(s[2 * u + 1][2], s[2 * u + 1][3]);
#pragma unroll
            for (int ep = 0; ep < 4; ep++) {
                int key = u * 16 + ((l >> 3) & 1) * 8 + (l & 7);
                int chunk = ep * 2 + (l >> 4);
                uint32_t r0, r1, r2, r3;
                ldsm_x4t(r0, r1, r2, r3, vb + aswz(key, chunk));
                mma_f16(acc[ep * 2],     a, r0, r1);
                mma_f16(acc[ep * 2 + 1], a, r2, r3);
            }
        }
        __syncthreads();
    }

    // ---- epilogue: O = acc / l  (fp16 out) ----
    float inv0 = 1.f / l0, inv1 = 1.f / l1;
    size_t o0 = ((size_t)(b * 1024 + q0 + qr + g)) * 1024 + h * 64;
    size_t o1 = o0 + (size_t)8 * 1024;
#pragma unroll
    for (int e = 0; e < 8; e++) {
        *(uint32_t*)&Octx[o0 + e * 8 + 2 * t] = h2bits(acc[e][0] * inv0, acc[e][1] * inv0);
        *(uint32_t*)&Octx[o1 + e * 8 + 2 * t] = h2bits(acc[e][2] * inv1, acc[e][3] * inv1);
    }
}

// ---------------------------------------------------------------------------
// LayerNorm (1024) -> fp16 output. One block (256 threads) per row.
// ---------------------------------------------------------------------------
__global__ void layernorm_k(const float* __restrict__ x, const float* __restrict__ g,
                            const float* __restrict__ b, __half* __restrict__ o)
{
    int row = blockIdx.x;
    const float4* xr = (const float4*)(x + (size_t)row * 1024);
    float4 v = xr[threadIdx.x];
    float s  = v.x + v.y + v.z + v.w;
    float ss = fmaf(v.x, v.x, fmaf(v.y, v.y, fmaf(v.z, v.z, v.w * v.w)));
#pragma unroll
    for (int off = 16; off > 0; off >>= 1) {
        s  += __shfl_xor_sync(0xffffffffu, s,  off);
        ss += __shfl_xor_sync(0xffffffffu, ss, off);
    }
    __shared__ float ws[8], wss[8];
    __shared__ float s_mean, s_inv;
    int w = threadIdx.x >> 5, ln = threadIdx.x & 31;
    if (ln == 0) { ws[w] = s; wss[w] = ss; }
    __syncthreads();
    if (threadIdx.x == 0) {
        float S = 0.f, SS = 0.f;
#pragma unroll
        for (int i = 0; i < 8; i++) { S += ws[i]; SS += wss[i]; }
        float mean = S * (1.f / 1024.f);
        float var  = SS * (1.f / 1024.f) - mean * mean;
        s_mean = mean;
        s_inv  = rsqrtf(var + 1e-5f);
    }
    __syncthreads();
    float mean = s_mean, inv = s_inv;
    float4 gv = ((const float4*)g)[threadIdx.x];
    float4 bv = ((const float4*)b)[threadIdx.x];
    uint2 r;
    r.x = h2bits((v.x - mean) * inv * gv.x + bv.x, (v.y - mean) * inv * gv.y + bv.y);
    r.y = h2bits((v.z - mean) * inv * gv.z + bv.z, (v.w - mean) * inv * gv.w + bv.w);
    *(uint2*)&o[(size_t)row * 1024 + threadIdx.x * 4] = r;
}

// ---------------------------------------------------------------------------
// Small kernels
// ---------------------------------------------------------------------------
__global__ void cvt_k(const float* __restrict__ src, __half* __restrict__ dst, int n)
{
    int i = blockIdx.x * blockDim.x + threadIdx.x;
    if (i < n) dst[i] = __float2half(src[i]);
}

__global__ void build_pe_k(const float* __restrict__ pos, const float* __restrict__ tim,
                           __half* __restrict__ pe)
{
    int i = blockIdx.x * blockDim.x + threadIdx.x;   // S*D
    int s = i >> 10, d = i & 1023;
    float v = (d < 512) ? pos[s * 512 + d] : tim[s * 512 + (d - 512)];
    pe[i] = __float2half(v);
}

__global__ void add_pe_k(const float* __restrict__ xin, const float* __restrict__ pep,
                         float* __restrict__ x)
{
    size_t i = (size_t)blockIdx.x * blockDim.x + threadIdx.x;
    x[i] = xin[i] + pep[i & ((size_t)(1 << 20) - 1)];
}

__global__ void softmax5_k(const float* __restrict__ elw, float* __restrict__ wsm,
                           float* __restrict__ out_w)
{
    if (threadIdx.x == 0) {
        float m = elw[0];
        for (int p = 1; p < 5; p++) m = fmaxf(m, elw[p]);
        float e[5], s = 0.f;
        for (int p = 0; p < 5; p++) { e[p] = expf(elw[p] - m); s += e[p]; }
        float inv = 1.f / s;
        for (int p = 0; p < 5; p++) { wsm[p] = e[p] * inv; out_w[p] = e[p] * inv; }
    }
}

__global__ void combine_w5_k(const float* __restrict__ ew, const float* __restrict__ wsm,
                             __half* __restrict__ w5)
{
    int i = blockIdx.x * blockDim.x + threadIdx.x;   // D*D
    float w0 = wsm[0], w1 = wsm[1], w2 = wsm[2], w3 = wsm[3], w4 = wsm[4];
    const size_t DD = (size_t)1024 * 1024;
    float v = w0 * ew[i] + w1 * ew[DD + i] + w2 * ew[2 * DD + i]
            + w3 * ew[3 * DD + i] + w4 * ew[4 * DD + i];
    w5[i] = __float2half(v);
}

__global__ void combine_b5_k(const float* __restrict__ eb, const float* __restrict__ wsm,
                             float* __restrict__ b5)
{
    int i = blockIdx.x * blockDim.x + threadIdx.x;   // D
    float v = 0.f;
    for (int p = 0; p < 5; p++) v += wsm[p] * eb[p * 1024 + i];
    b5[i] = v;
}

__global__ void pack_qkvm_k(const float* __restrict__ qw, const float* __restrict__ kw,
                            const float* __restrict__ vw, const float* __restrict__ mw1,
                            const float* __restrict__ qb, const float* __restrict__ kb,
                            const float* __restrict__ vb, const float* __restrict__ mb1,
                            __half* __restrict__ wq, float* __restrict__ bq)
{
    int i = blockIdx.x * blockDim.x + threadIdx.x;   // D * 3584
    int k = i / NQKV, n = i - k * NQKV;
    float v;
    if (n < 1024)      v = qw[k * 1024 + n];
    else if (n < 2048) v = kw[k * 1024 + n - 1024];
    else if (n < 3072) v = vw[k * 1024 + n - 2048];
    else               v = mw1[k * 512 + n - 3072];
    wq[i] = __float2half(v);
    if (i < NQKV) {
        float b;
        if (i < 1024)      b = qb[i];
        else if (i < 2048) b = kb[i - 1024];
        else if (i < 3072) b = vb[i - 2048];
        else               b = mb1[i - 3072];
        bq[i] = b;
    }
}

// mech[r] = sigmoid(dot(qkv16[r, 3072:3584], mw2) + mb2); one warp per row.
__global__ void mech_out_k(const __half* __restrict__ qkv, const float* __restrict__ mw2,
                           const float* __restrict__ mb2, float* __restrict__ mech,
                           float* __restrict__ out_mech)
{
    int row  = blockIdx.x * 8 + (threadIdx.x >> 5);
    int lane = threadIdx.x & 31;
    const __half* r = qkv + (size_t)row * NQKV + 3072;
    float s = 0.f;
#pragma unroll
    for (int c = lane; c < 512; c += 32) s = fmaf(__half2float(r[c]), mw2[c], s);
#pragma unroll
    for (int off = 16; off > 0; off >>= 1) s += __shfl_xor_sync(0xffffffffu, s, off);
    if (lane == 0) {
        float t = s + mb2[0];
        float m = 1.f / (1.f + expf(-t));
        mech[row] = m;
        out_mech[row] = m;
    }
}

// ---------------------------------------------------------------------------
// Host launcher
// ---------------------------------------------------------------------------
extern "C" void kernel_launch(void* const* d_in, const int* in_sizes, int n_in,
                              void* d_out, int out_size)
{
    (void)in_sizes; (void)n_in; (void)out_size;
    const float* x_in = (const float*)d_in[0];
    const float* pos  = (const float*)d_in[1];
    const float* tim  = (const float*)d_in[2];
    const float* wi   = (const float*)d_in[3];
    const float* bi   = (const float*)d_in[4];
    const float* g1   = (const float*)d_in[5];
    const float* be1  = (const float*)d_in[6];
    const float* g2   = (const float*)d_in[7];
    const float* be2  = (const float*)d_in[8];
    const float* g3   = (const float*)d_in[9];
    const float* be3  = (const float*)d_in[10];
    const float* qw   = (const float*)d_in[11];
    const float* qb   = (const float*)d_in[12];
    const float* kw   = (const float*)d_in[13];
    const float* kb   = (const float*)d_in[14];
    const float* vw   = (const float*)d_in[15];
    const float* vb   = (const float*)d_in[16];
    const float* ow   = (const float*)d_in[17];
    const float* ob   = (const float*)d_in[18];
    const float* mw1  = (const float*)d_in[19];
    const float* mb1  = (const float*)d_in[20];
    const float* mw2  = (const float*)d_in[21];
    const float* mb2  = (const float*)d_in[22];
    const float* ew   = (const float*)d_in[23];
    const float* eb   = (const float*)d_in[24];
    const float* elw  = (const float*)d_in[25];
    const float* fw1  = (const float*)d_in[26];
    const float* fb1  = (const float*)d_in[27];
    const float* fw2  = (const float*)d_in[28];
    const float* fb2  = (const float*)d_in[29];

    float* out = (float*)d_out;
    float* out_mech = out + NXD;
    float* out_w    = out + NXD + BS;

    float* fb = nullptr;
    cudaGetSymbolAddress((void**)&fb, g_buf);
    float* gx    = fb + OFF_X;
    float* gpep  = fb + OFF_PEP;
    float* gmech = fb + OFF_MECH;
    float* gb5   = fb + OFF_B5;
    float* gwsm  = fb + OFF_WSM;
    float* gbqkv = fb + OFF_BQKV;

    __half *h16, *qkv16, *ctx16, *ffh16, *pe16, *w16;
    cudaGetSymbolAddress((void**)&h16,   g_h16);
    cudaGetSymbolAddress((void**)&qkv16, g_qkv16);
    cudaGetSymbolAddress((void**)&ctx16, g_ctx16);
    cudaGetSymbolAddress((void**)&ffh16, g_ffh16);
    cudaGetSymbolAddress((void**)&pe16,  g_pe16);
    cudaGetSymbolAddress((void**)&w16,   g_w16);

    // weight conversions (fp32 -> fp16), once per launch
    cvt_k<<<(Dc * Dc) / 256, 256>>>(wi,  w16 + W16_WI,  Dc * Dc);
    cvt_k<<<(Dc * Dc) / 256, 256>>>(ow,  w16 + W16_OW,  Dc * Dc);
    cvt_k<<<(Dc * DFFc) / 256, 256>>>(fw1, w16 + W16_FW1, Dc * DFFc);
    cvt_k<<<(DFFc * Dc) / 256, 256>>>(fw2, w16 + W16_FW2, DFFc * Dc);
    pack_qkvm_k<<<(Dc * NQKV) / 256, 256>>>(qw, kw, vw, mw1, qb, kb, vb, mb1,
                                            w16 + W16_QKV, gbqkv);

    // 1) positional/timing embedding
    build_pe_k<<<(Sc * Dc) / 256, 256>>>(pos, tim, pe16);
    hgemm_k<<<dim3(Dc / 128, Sc / 128), 256>>>(pe16, w16 + W16_WI, bi, nullptr, gpep,
                                               Sc, Dc, Dc, 0, 0);
    add_pe_k<<<(unsigned)(NXD / 256), 256>>>(x_in, gpep, gx);

    // 2) norm1 -> h16
    layernorm_k<<<BS, 256>>>(gx, g1, be1, h16);

    // 3) fused QKV + mech-hidden projection (fp16 out)
    hgemm_k<<<dim3(NQKV / 128, BS / 128), 256>>>(h16, w16 + W16_QKV, gbqkv, nullptr, qkv16,
                                                 BS, NQKV, Dc, 2, 1);

    // 4) mechanism output
    mech_out_k<<<BS / 8, 256>>>(qkv16, mw2, mb2, gmech, out_mech);

    // 5) fp16 flash attention (mech folded into K) -> ctx16
    attn_h_k<<<dim3(Sc / 128, Bc * Hc), 256>>>(qkv16, gmech, ctx16);

    // 6) output projection + residual
    hgemm_k<<<dim3(Dc / 128, BS / 128), 256>>>(ctx16, w16 + W16_OW, ob, gx, gx,
                                               BS, Dc, Dc, 0, 0);

    // 7) five elements (folded to one GEMM)
    layernorm_k<<<BS, 256>>>(gx, g2, be2, h16);
    softmax5_k<<<1, 32>>>(elw, gwsm, out_w);
    combine_w5_k<<<(Dc * Dc) / 256, 256>>>(ew, gwsm, w16 + W16_W5);
    combine_b5_k<<<Dc / 256, 256>>>(eb, gwsm, gb5);
    hgemm_k<<<dim3(Dc / 128, BS / 128), 256>>>(h16, w16 + W16_W5, gb5, gx, gx,
                                               BS, Dc, Dc, 0, 0);

    // 8) FFN
    layernorm_k<<<BS, 256>>>(gx, g3, be3, h16);
    hgemm_k<<<dim3(DFFc / 128, BS / 128), 256>>>(h16, w16 + W16_FW1, fb1, nullptr, ffh16,
                                                 BS, DFFc, Dc, 1, 1);
    hgemm_k<<<dim3(Dc / 128, BS / 128), 256>>>(ffh16, w16 + W16_FW2, fb2, gx, out,
                                               BS, Dc, DFFc, 0, 0);
}

// round 8
// speedup vs baseline: 6.6933x; 1.2714x over previous
#include <cuda_runtime.h>
#include <cuda_fp16.h>
#include <math.h>
#include <stdint.h>

// ---------------------------------------------------------------------------
// MechanismTransformerBlock  B=8 S=1024 D=1024 H=16 DH=64 DFF=4096
// fp16 tensor-core path; hgemm with 3-stage cp.async pipeline;
// fp16 flash attention; fused add_pe+LN1; vectorized prep kernels.
// ---------------------------------------------------------------------------

namespace {
constexpr int Bc = 8, Sc = 1024, Dc = 1024, Hc = 16, DFFc = 4096;
constexpr int BS = Bc * Sc;                       // 8192 rows
constexpr size_t NXD = (size_t)BS * Dc;           // 8,388,608
constexpr int NQKV = 3584;                        // q|k|v|mech-hidden

// fp32 scratch
constexpr size_t OFF_X    = 0;
constexpr size_t OFF_PEP  = OFF_X   + NXD;                    // S x D
constexpr size_t OFF_MECH = OFF_PEP + (size_t)Sc * Dc;        // BS
constexpr size_t OFF_B5   = OFF_MECH+ (size_t)BS;             // D
constexpr size_t OFF_WSM  = OFF_B5  + Dc;                     // 8
constexpr size_t OFF_BQKV = OFF_WSM + 8;                      // 3584
constexpr size_t TOTALF   = OFF_BQKV + NQKV;

// fp16 weight staging offsets (in halfs)
constexpr size_t W16_WI  = 0;
constexpr size_t W16_OW  = W16_WI  + (size_t)Dc * Dc;
constexpr size_t W16_W5  = W16_OW  + (size_t)Dc * Dc;
constexpr size_t W16_FW1 = W16_W5  + (size_t)Dc * Dc;
constexpr size_t W16_FW2 = W16_FW1 + (size_t)Dc * DFFc;
constexpr size_t W16_QKV = W16_FW2 + (size_t)DFFc * Dc;
constexpr size_t W16_TOT = W16_QKV + (size_t)Dc * NQKV;
}

__device__ float  g_buf[TOTALF];
__device__ __half g_h16[NXD];                 // LN output
__device__ __half g_qkv16[(size_t)BS * NQKV]; // q|k|v|mech-hidden
__device__ __half g_ctx16[NXD];               // attention output
__device__ __half g_ffh16[(size_t)BS * DFFc]; // FFN hidden
__device__ __half g_pe16[(size_t)Sc * Dc];
__device__ __half g_w16[W16_TOT];

__device__ __forceinline__ float gelu_exact(float v) {
    return 0.5f * v * (1.0f + erff(v * 0.70710678118654752440f));
}

__device__ __forceinline__ void mma_f16(float* c, const uint32_t* a, uint32_t b0, uint32_t b1) {
    asm volatile(
        "mma.sync.aligned.m16n8k16.row.col.f32.f16.f16.f32 "
        "{%0,%1,%2,%3}, {%4,%5,%6,%7}, {%8,%9}, {%0,%1,%2,%3};\n"
        : "+f"(c[0]), "+f"(c[1]), "+f"(c[2]), "+f"(c[3])
        : "r"(a[0]), "r"(a[1]), "r"(a[2]), "r"(a[3]), "r"(b0), "r"(b1));
}

__device__ __forceinline__ void ldsm_x4(uint32_t& r0, uint32_t& r1, uint32_t& r2, uint32_t& r3,
                                        uint32_t addr) {
    asm volatile("ldmatrix.sync.aligned.m8n8.x4.shared.b16 {%0,%1,%2,%3}, [%4];"
                 : "=r"(r0), "=r"(r1), "=r"(r2), "=r"(r3) : "r"(addr));
}

__device__ __forceinline__ void ldsm_x4t(uint32_t& r0, uint32_t& r1, uint32_t& r2, uint32_t& r3,
                                         uint32_t addr) {
    asm volatile("ldmatrix.sync.aligned.m8n8.x4.trans.shared.b16 {%0,%1,%2,%3}, [%4];"
                 : "=r"(r0), "=r"(r1), "=r"(r2), "=r"(r3) : "r"(addr));
}

__device__ __forceinline__ uint32_t h2bits(float lo, float hi) {
    __half2 h = __floats2half2_rn(lo, hi);
    return *reinterpret_cast<uint32_t*>(&h);
}

__device__ __forceinline__ void cp16(uint32_t smem, const void* g) {
    asm volatile("cp.async.cg.shared.global [%0], [%1], 16;" :: "r"(smem), "l"(g));
}
__device__ __forceinline__ void cp_commit() {
    asm volatile("cp.async.commit_group;");
}
template <int N>
__device__ __forceinline__ void cp_wait() {
    asm volatile("cp.async.wait_group %0;" :: "n"(N));
}

// ---------------------------------------------------------------------------
// fp16 GEMM, 3-stage cp.async pipeline.
// 128x128 tile, BK=16, 256 thr = 8 warps (4M x 2N), warp tile 32x64.
// A smem stage 4KB [m][16] swz c^((m>>2)&1); B stage 4KB [k][128] swz c^(k&7).
// A ring at 0..12KB, B ring at 12..24KB.
// act: 0 none, 1 gelu, 2 gelu iff global col >= 3072.
// ---------------------------------------------------------------------------
__global__ void __launch_bounds__(256, 2)
hgemm_k(const __half* __restrict__ A, const __half* __restrict__ Bm,
        const float* __restrict__ bias, const float* __restrict__ resid,
        void* __restrict__ Cv, int M, int N, int K, int act, int outh)
{
    __shared__ __align__(16) unsigned char smem[6 * 4096];
    const uint32_t smem_base = (uint32_t)__cvta_generic_to_shared(smem);

    const int tid = threadIdx.x;
    const int w = tid >> 5, l = tid & 31;
    const int wm = (w & 3) * 32;
    const int wn = (w >> 2) * 64;
    const int g = l >> 2, t = l & 3;
    const int bn = blockIdx.x, bm = blockIdx.y;
    const __half* Ab = A + (size_t)bm * 128 * K;
    const __half* Bb = Bm + (size_t)bn * 128;

    const int arow = tid >> 1;            // 0..127
    const int ac   = tid & 1;
    const int brow = tid >> 4;            // 0..15
    const int bc   = tid & 15;

    const uint32_t a_st = smem_base + arow * 32 + ((ac ^ ((arow >> 2) & 1)) << 4);
    const uint32_t b_st = smem_base + 12288 + brow * 256 + ((bc ^ (brow & 7)) << 4);
    const __half* a_gp = Ab + (size_t)arow * K + ac * 8;
    const __half* b_gp = Bb + (size_t)brow * N + bc * 8;

    const int amr = ((l >> 3) & 1) * 8 + (l & 7);
    const int acf = l >> 4;
    const int bkk = ((l >> 4) & 1) * 8 + (l & 7);
    const int bcb = (wn >> 3) + ((l >> 3) & 1);

    const int NIT = K >> 4;

    float acc[2][8][4];
#pragma unroll
    for (int i = 0; i < 2; i++)
#pragma unroll
        for (int j = 0; j < 8; j++)
#pragma unroll
            for (int r = 0; r < 4; r++) acc[i][j][r] = 0.f;

    // prologue: stages 0,1
#pragma unroll
    for (int s = 0; s < 2; s++) {
        cp16(a_st + s * 4096, a_gp + s * 16);
        cp16(b_st + s * 4096, b_gp + (size_t)(s * 16) * N);
        cp_commit();
    }

    int st = 0;
    for (int it = 0; it < NIT; it++) {
        cp_wait<1>();            // stage it arrived
        __syncthreads();         // all warps past MMA(it-1); stage (it+2)%3 free
        {
            int nx = it + 2;
            if (nx < NIT) {
                int ring = nx - (nx / 3) * 3;
                cp16(a_st + ring * 4096, a_gp + nx * 16);
                cp16(b_st + ring * 4096, b_gp + (size_t)(nx * 16) * N);
            }
            cp_commit();
        }
        {
            const uint32_t abuf = smem_base + st * 4096;
            const uint32_t bbuf = smem_base + 12288 + st * 4096;
            uint32_t af[2][4];
#pragma unroll
            for (int i = 0; i < 2; i++) {
                int m = wm + i * 16 + amr;
                uint32_t ad = abuf + m * 32 + ((acf ^ ((m >> 2) & 1)) << 4);
                ldsm_x4(af[i][0], af[i][1], af[i][2], af[i][3], ad);
            }
#pragma unroll
            for (int jp = 0; jp < 4; jp++) {
                int cB = bcb + jp * 2;
                uint32_t bd = bbuf + bkk * 256 + ((cB ^ (bkk & 7)) << 4);
                uint32_t r0, r1, r2, r3;
                ldsm_x4t(r0, r1, r2, r3, bd);
#pragma unroll
                for (int i = 0; i < 2; i++) {
                    mma_f16(acc[i][jp * 2],     af[i], r0, r2);
                    mma_f16(acc[i][jp * 2 + 1], af[i], r1, r3);
                }
            }
        }
        st++; if (st == 3) st = 0;
    }

#pragma unroll
    for (int i = 0; i < 2; i++) {
        int row0 = bm * 128 + wm + i * 16 + g;
        int row1 = row0 + 8;
        size_t ro0 = (size_t)row0 * N;
        size_t ro1 = (size_t)row1 * N;
#pragma unroll
        for (int j = 0; j < 8; j++) {
            int col = bn * 128 + wn + j * 8 + 2 * t;
            float v0 = acc[i][j][0], v1 = acc[i][j][1];
            float v2 = acc[i][j][2], v3 = acc[i][j][3];
            if (bias) {
                float b0 = bias[col], b1 = bias[col + 1];
                v0 += b0; v1 += b1; v2 += b0; v3 += b1;
            }
            bool dg = (act == 1) || (act == 2 && col >= 3072);
            if (dg) {
                v0 = gelu_exact(v0); v1 = gelu_exact(v1);
                v2 = gelu_exact(v2); v3 = gelu_exact(v3);
            }
            if (resid) {
                v0 += resid[ro0 + col]; v1 += resid[ro0 + col + 1];
                v2 += resid[ro1 + col]; v3 += resid[ro1 + col + 1];
            }
            if (outh) {
                __half* C = (__half*)Cv;
                *(uint32_t*)&C[ro0 + col] = h2bits(v0, v1);
                *(uint32_t*)&C[ro1 + col] = h2bits(v2, v3);
            } else {
                float* C = (float*)Cv;
                *(float2*)&C[ro0 + col] = make_float2(v0, v1);
                *(float2*)&C[ro1 + col] = make_float2(v2, v3);
            }
        }
    }
}

// ---------------------------------------------------------------------------
// fp16 flash attention.  QKV fp16 [BS][3584]; mech factor folded into K.
// ---------------------------------------------------------------------------
__device__ __forceinline__ uint32_t aswz(int r, int c) {
    return (uint32_t)(r * 128 + ((c ^ ((r + (r >> 3)) & 7)) << 4));
}

__global__ void __launch_bounds__(256)
attn_h_k(const __half* __restrict__ QKV, const float* __restrict__ mech,
         __half* __restrict__ Octx)
{
    __shared__ __align__(16) __half smem[16384];   // Q 16KB | K 8KB | V 8KB
    const uint32_t sb = (uint32_t)__cvta_generic_to_shared(smem);
    const uint32_t kb = sb + 16384;
    const uint32_t vb = sb + 24576;

    const int tid = threadIdx.x;
    const int w = tid >> 5, l = tid & 31;
    const int g = l >> 2, t = l & 3;
    const int bh = blockIdx.y;
    const int b = bh >> 4, h = bh & 15;
    const int q0 = blockIdx.x * 128;
    const int qr = w * 16;

    {
        int r = tid >> 1;
        int c0 = (tid & 1) * 4;
        const __half* qp = QKV + ((size_t)(b * 1024 + q0 + r)) * NQKV + h * 64;
#pragma unroll
        for (int u = 0; u < 4; u++) {
            int c = c0 + u;
            uint4 v = *(const uint4*)(qp + c * 8);
            asm volatile("st.shared.v4.u32 [%0], {%1,%2,%3,%4};" ::
                         "r"(sb + aswz(r, c)), "r"(v.x), "r"(v.y), "r"(v.z), "r"(v.w));
        }
    }

    float m0 = -1e30f, m1 = -1e30f, l0 = 0.f, l1 = 0.f;
    float acc[8][4];
#pragma unroll
    for (int e = 0; e < 8; e++)
#pragma unroll
        for (int r = 0; r < 4; r++) acc[e][r] = 0.f;
    __syncthreads();

    for (int kt = 0; kt < 16; kt++) {
        const int k0 = kt * 64;
        {
            int r = tid >> 2;
            int c0 = (tid & 3) * 2;
            size_t rowb = ((size_t)(b * 1024 + k0 + r)) * NQKV + h * 64;
            float f = 0.125f * (1.f + mech[(size_t)b * 1024 + k0 + r]);
            __half2 fh = __float2half2_rn(f);
            const __half* kp = QKV + rowb + 1024;
            const __half* vp = QKV + rowb + 2048;
#pragma unroll
            for (int u = 0; u < 2; u++) {
                int c = c0 + u;
                uint4 kv = *(const uint4*)(kp + c * 8);
                __half2* kh = (__half2*)&kv;
                kh[0] = __hmul2(kh[0], fh);
                kh[1] = __hmul2(kh[1], fh);
                kh[2] = __hmul2(kh[2], fh);
                kh[3] = __hmul2(kh[3], fh);
                asm volatile("st.shared.v4.u32 [%0], {%1,%2,%3,%4};" ::
                             "r"(kb + aswz(r, c)), "r"(kv.x), "r"(kv.y), "r"(kv.z), "r"(kv.w));
                uint4 vv = *(const uint4*)(vp + c * 8);
                asm volatile("st.shared.v4.u32 [%0], {%1,%2,%3,%4};" ::
                             "r"(vb + aswz(r, c)), "r"(vv.x), "r"(vv.y), "r"(vv.z), "r"(vv.w));
            }
        }
        __syncthreads();

        float s[8][4];
#pragma unroll
        for (int j = 0; j < 8; j++)
#pragma unroll
            for (int r = 0; r < 4; r++) s[j][r] = 0.f;
#pragma unroll
        for (int kc = 0; kc < 4; kc++) {
            uint32_t a[4];
            {
                int row = qr + (l & 7) + ((l >> 3) & 1) * 8;
                int chunk = 2 * kc + (l >> 4);
                ldsm_x4(a[0], a[1], a[2], a[3], sb + aswz(row, chunk));
            }
#pragma unroll
            for (int jp = 0; jp < 4; jp++) {
                int key = jp * 16 + ((l >> 4) & 1) * 8 + (l & 7);
                int chunk = 2 * kc + ((l >> 3) & 1);
                uint32_t r0, r1, r2, r3;
                ldsm_x4(r0, r1, r2, r3, kb + aswz(key, chunk));
                mma_f16(s[jp * 2],     a, r0, r1);
                mma_f16(s[jp * 2 + 1], a, r2, r3);
            }
        }

        float mx0 = -1e30f, mx1 = -1e30f;
#pragma unroll
        for (int j = 0; j < 8; j++) {
            mx0 = fmaxf(mx0, fmaxf(s[j][0], s[j][1]));
            mx1 = fmaxf(mx1, fmaxf(s[j][2], s[j][3]));
        }
        mx0 = fmaxf(mx0, __shfl_xor_sync(0xffffffffu, mx0, 1));
        mx0 = fmaxf(mx0, __shfl_xor_sync(0xffffffffu, mx0, 2));
        mx1 = fmaxf(mx1, __shfl_xor_sync(0xffffffffu, mx1, 1));
        mx1 = fmaxf(mx1, __shfl_xor_sync(0xffffffffu, mx1, 2));
        float mn0 = fmaxf(m0, mx0), mn1 = fmaxf(m1, mx1);
        float al0 = __expf(m0 - mn0), al1 = __expf(m1 - mn1);
        float sum0 = 0.f, sum1 = 0.f;
#pragma unroll
        for (int j = 0; j < 8; j++) {
            s[j][0] = __expf(s[j][0] - mn0);
            s[j][1] = __expf(s[j][1] - mn0);
            s[j][2] = __expf(s[j][2] - mn1);
            s[j][3] = __expf(s[j][3] - mn1);
            sum0 += s[j][0] + s[j][1];
            sum1 += s[j][2] + s[j][3];
        }
        sum0 += __shfl_xor_sync(0xffffffffu, sum0, 1);
        sum0 += __shfl_xor_sync(0xffffffffu, sum0, 2);
        sum1 += __shfl_xor_sync(0xffffffffu, sum1, 1);
        sum1 += __shfl_xor_sync(0xffffffffu, sum1, 2);
        l0 = l0 * al0 + sum0;
        l1 = l1 * al1 + sum1;
        m0 = mn0; m1 = mn1;
#pragma unroll
        for (int e = 0; e < 8; e++) {
            acc[e][0] *= al0; acc[e][1] *= al0;
            acc[e][2] *= al1; acc[e][3] *= al1;
        }

#pragma unroll
        for (int u = 0; u < 4; u++) {
            uint32_t a[4];
            a[0] = h2bits(s[2 * u][0],     s[2 * u][1]);
            a[1] = h2bits(s[2 * u][2],     s[2 * u][3]);
            a[2] = h2bits(s[2 * u + 1][0], s[2 * u + 1][1]);
            a[3] = h2bits(s[2 * u + 1][2], s[2 * u + 1][3]);
#pragma unroll
            for (int ep = 0; ep < 4; ep++) {
                int key = u * 16 + ((l >> 3) & 1) * 8 + (l & 7);
                int chunk = ep * 2 + (l >> 4);
                uint32_t r0, r1, r2, r3;
                ldsm_x4t(r0, r1, r2, r3, vb + aswz(key, chunk));
                mma_f16(acc[ep * 2],     a, r0, r1);
                mma_f16(acc[ep * 2 + 1], a, r2, r3);
            }
        }
        __syncthreads();
    }

    float inv0 = 1.f / l0, inv1 = 1.f / l1;
    size_t o0 = ((size_t)(b * 1024 + q0 + qr + g)) * 1024 + h * 64;
    size_t o1 = o0 + (size_t)8 * 1024;
#pragma unroll
    for (int e = 0; e < 8; e++) {
        *(uint32_t*)&Octx[o0 + e * 8 + 2 * t] = h2bits(acc[e][0] * inv0, acc[e][1] * inv0);
        *(uint32_t*)&Octx[o1 + e * 8 + 2 * t] = h2bits(acc[e][2] * inv1, acc[e][3] * inv1);
    }
}

// ---------------------------------------------------------------------------
// LayerNorm (1024) -> fp16. One block per row.
// ---------------------------------------------------------------------------
__global__ void layernorm_k(const float* __restrict__ x, const float* __restrict__ g,
                            const float* __restrict__ b, __half* __restrict__ o)
{
    int row = blockIdx.x;
    const float4* xr = (const float4*)(x + (size_t)row * 1024);
    float4 v = xr[threadIdx.x];
    float s  = v.x + v.y + v.z + v.w;
    float ss = fmaf(v.x, v.x, fmaf(v.y, v.y, fmaf(v.z, v.z, v.w * v.w)));
#pragma unroll
    for (int off = 16; off > 0; off >>= 1) {
        s  += __shfl_xor_sync(0xffffffffu, s,  off);
        ss += __shfl_xor_sync(0xffffffffu, ss, off);
    }
    __shared__ float ws[8], wss[8];
    __shared__ float s_mean, s_inv;
    int w = threadIdx.x >> 5, ln = threadIdx.x & 31;
    if (ln == 0) { ws[w] = s; wss[w] = ss; }
    __syncthreads();
    if (threadIdx.x == 0) {
        float S = 0.f, SS = 0.f;
#pragma unroll
        for (int i = 0; i < 8; i++) { S += ws[i]; SS += wss[i]; }
        float mean = S * (1.f / 1024.f);
        float var  = SS * (1.f / 1024.f) - mean * mean;
        s_mean = mean;
        s_inv  = rsqrtf(var + 1e-5f);
    }
    __syncthreads();
    float mean = s_mean, inv = s_inv;
    float4 gv = ((const float4*)g)[threadIdx.x];
    float4 bv = ((const float4*)b)[threadIdx.x];
    uint2 r;
    r.x = h2bits((v.x - mean) * inv * gv.x + bv.x, (v.y - mean) * inv * gv.y + bv.y);
    r.y = h2bits((v.z - mean) * inv * gv.z + bv.z, (v.w - mean) * inv * gv.w + bv.w);
    *(uint2*)&o[(size_t)row * 1024 + threadIdx.x * 4] = r;
}

// Fused: x = x_in + pep (write fp32 residual) AND layernorm(x) -> fp16.
__global__ void ln_addpe_k(const float* __restrict__ xin, const float* __restrict__ pep,
                           const float* __restrict__ g, const float* __restrict__ b,
                           float* __restrict__ xo, __half* __restrict__ o)
{
    int row = blockIdx.x;
    float4 xi = ((const float4*)(xin + (size_t)row * 1024))[threadIdx.x];
    float4 pe = ((const float4*)(pep + (size_t)(row & 1023) * 1024))[threadIdx.x];
    float4 v = make_float4(xi.x + pe.x, xi.y + pe.y, xi.z + pe.z, xi.w + pe.w);
    ((float4*)(xo + (size_t)row * 1024))[threadIdx.x] = v;
    float s  = v.x + v.y + v.z + v.w;
    float ss = fmaf(v.x, v.x, fmaf(v.y, v.y, fmaf(v.z, v.z, v.w * v.w)));
#pragma unroll
    for (int off = 16; off > 0; off >>= 1) {
        s  += __shfl_xor_sync(0xffffffffu, s,  off);
        ss += __shfl_xor_sync(0xffffffffu, ss, off);
    }
    __shared__ float ws[8], wss[8];
    __shared__ float s_mean, s_inv;
    int w = threadIdx.x >> 5, ln = threadIdx.x & 31;
    if (ln == 0) { ws[w] = s; wss[w] = ss; }
    __syncthreads();
    if (threadIdx.x == 0) {
        float S = 0.f, SS = 0.f;
#pragma unroll
        for (int i = 0; i < 8; i++) { S += ws[i]; SS += wss[i]; }
        float mean = S * (1.f / 1024.f);
        float var  = SS * (1.f / 1024.f) - mean * mean;
        s_mean = mean;
        s_inv  = rsqrtf(var + 1e-5f);
    }
    __syncthreads();
    float mean = s_mean, inv = s_inv;
    float4 gv = ((const float4*)g)[threadIdx.x];
    float4 bv = ((const float4*)b)[threadIdx.x];
    uint2 r;
    r.x = h2bits((v.x - mean) * inv * gv.x + bv.x, (v.y - mean) * inv * gv.y + bv.y);
    r.y = h2bits((v.z - mean) * inv * gv.z + bv.z, (v.w - mean) * inv * gv.w + bv.w);
    *(uint2*)&o[(size_t)row * 1024 + threadIdx.x * 4] = r;
}

// ---------------------------------------------------------------------------
// Prep kernels (vectorized: 8 elems/thread)
// ---------------------------------------------------------------------------
__global__ void cvt8_k(const float4* __restrict__ src, uint4* __restrict__ dst, int n8)
{
    int i = blockIdx.x * blockDim.x + threadIdx.x;
    if (i >= n8) return;
    float4 a = src[2 * i], b = src[2 * i + 1];
    dst[i] = make_uint4(h2bits(a.x, a.y), h2bits(a.z, a.w),
                        h2bits(b.x, b.y), h2bits(b.z, b.w));
}

__global__ void build_pe_k(const float* __restrict__ pos, const float* __restrict__ tim,
                           __half* __restrict__ pe)
{
    int i = (blockIdx.x * blockDim.x + threadIdx.x) * 4;   // S*D
    int s = i >> 10, d = i & 1023;
    const float* srcp = (d < 512) ? pos + s * 512 + d : tim + s * 512 + (d - 512);
    float4 v = *(const float4*)srcp;
    *(uint2*)&pe[i] = make_uint2(h2bits(v.x, v.y), h2bits(v.z, v.w));
}

__global__ void softmax5_k(const float* __restrict__ elw, float* __restrict__ wsm,
                           float* __restrict__ out_w)
{
    if (threadIdx.x == 0) {
        float m = elw[0];
        for (int p = 1; p < 5; p++) m = fmaxf(m, elw[p]);
        float e[5], s = 0.f;
        for (int p = 0; p < 5; p++) { e[p] = expf(elw[p] - m); s += e[p]; }
        float inv = 1.f / s;
        for (int p = 0; p < 5; p++) { wsm[p] = e[p] * inv; out_w[p] = e[p] * inv; }
    }
}

__global__ void combine_w5_k(const float* __restrict__ ew, const float* __restrict__ wsm,
                             __half* __restrict__ w5)
{
    int i = (blockIdx.x * blockDim.x + threadIdx.x) * 4;   // D*D
    float w0 = wsm[0], w1 = wsm[1], w2 = wsm[2], w3 = wsm[3], w4 = wsm[4];
    const size_t DD = (size_t)1024 * 1024;
    float4 e0 = *(const float4*)&ew[i];
    float4 e1 = *(const float4*)&ew[DD + i];
    float4 e2 = *(const float4*)&ew[2 * DD + i];
    float4 e3 = *(const float4*)&ew[3 * DD + i];
    float4 e4 = *(const float4*)&ew[4 * DD + i];
    float vx = w0 * e0.x + w1 * e1.x + w2 * e2.x + w3 * e3.x + w4 * e4.x;
    float vy = w0 * e0.y + w1 * e1.y + w2 * e2.y + w3 * e3.y + w4 * e4.y;
    float vz = w0 * e0.z + w1 * e1.z + w2 * e2.z + w3 * e3.z + w4 * e4.z;
    float vw = w0 * e0.w + w1 * e1.w + w2 * e2.w + w3 * e3.w + w4 * e4.w;
    *(uint2*)&w5[i] = make_uint2(h2bits(vx, vy), h2bits(vz, vw));
}

__global__ void combine_b5_k(const float* __restrict__ eb, const float* __restrict__ wsm,
                             float* __restrict__ b5)
{
    int i = blockIdx.x * blockDim.x + threadIdx.x;   // D
    float v = 0.f;
    for (int p = 0; p < 5; p++) v += wsm[p] * eb[p * 1024 + i];
    b5[i] = v;
}

// Pack qw|kw|vw|mw1 -> fp16 [D][3584]; biases -> fp32 [3584]. 8 cols/thread.
__global__ void pack_qkvm_k(const float* __restrict__ qw, const float* __restrict__ kw,
                            const float* __restrict__ vw, const float* __restrict__ mw1,
                            const float* __restrict__ qb, const float* __restrict__ kb,
                            const float* __restrict__ vb, const float* __restrict__ mb1,
                            __half* __restrict__ wq, float* __restrict__ bq)
{
    int i = blockIdx.x * blockDim.x + threadIdx.x;   // D * 448
    int k = i / 448, n = (i - k * 448) * 8;
    const float* sp;
    if (n < 1024)      sp = qw  + k * 1024 + n;
    else if (n < 2048) sp = kw  + k * 1024 + (n - 1024);
    else if (n < 3072) sp = vw  + k * 1024 + (n - 2048);
    else               sp = mw1 + k * 512  + (n - 3072);
    float4 a = *(const float4*)sp;
    float4 b = *(const float4*)(sp + 4);
    *(uint4*)&wq[(size_t)k * NQKV + n] =
        make_uint4(h2bits(a.x, a.y), h2bits(a.z, a.w), h2bits(b.x, b.y), h2bits(b.z, b.w));
    if (i < NQKV) {
        float bb;
        if (i < 1024)      bb = qb[i];
        else if (i < 2048) bb = kb[i - 1024];
        else if (i < 3072) bb = vb[i - 2048];
        else               bb = mb1[i - 3072];
        bq[i] = bb;
    }
}

// mech[r] = sigmoid(dot(qkv16[r, 3072:3584], mw2) + mb2); one warp per row.
__global__ void mech_out_k(const __half* __restrict__ qkv, const float* __restrict__ mw2,
                           const float* __restrict__ mb2, float* __restrict__ mech,
                           float* __restrict__ out_mech)
{
    int row  = blockIdx.x * 8 + (threadIdx.x >> 5);
    int lane = threadIdx.x & 31;
    const __half* r = qkv + (size_t)row * NQKV + 3072;
    float s = 0.f;
#pragma unroll
    for (int c = lane; c < 512; c += 32) s = fmaf(__half2float(r[c]), mw2[c], s);
#pragma unroll
    for (int off = 16; off > 0; off >>= 1) s += __shfl_xor_sync(0xffffffffu, s, off);
    if (lane == 0) {
        float t = s + mb2[0];
        float m = 1.f / (1.f + expf(-t));
        mech[row] = m;
        out_mech[row] = m;
    }
}

// ---------------------------------------------------------------------------
// Host launcher
// ---------------------------------------------------------------------------
extern "C" void kernel_launch(void* const* d_in, const int* in_sizes, int n_in,
                              void* d_out, int out_size)
{
    (void)in_sizes; (void)n_in; (void)out_size;
    const float* x_in = (const float*)d_in[0];
    const float* pos  = (const float*)d_in[1];
    const float* tim  = (const float*)d_in[2];
    const float* wi   = (const float*)d_in[3];
    const float* bi   = (const float*)d_in[4];
    const float* g1   = (const float*)d_in[5];
    const float* be1  = (const float*)d_in[6];
    const float* g2   = (const float*)d_in[7];
    const float* be2  = (const float*)d_in[8];
    const float* g3   = (const float*)d_in[9];
    const float* be3  = (const float*)d_in[10];
    const float* qw   = (const float*)d_in[11];
    const float* qb   = (const float*)d_in[12];
    const float* kw   = (const float*)d_in[13];
    const float* kb   = (const float*)d_in[14];
    const float* vw   = (const float*)d_in[15];
    const float* vb   = (const float*)d_in[16];
    const float* ow   = (const float*)d_in[17];
    const float* ob   = (const float*)d_in[18];
    const float* mw1  = (const float*)d_in[19];
    const float* mb1  = (const float*)d_in[20];
    const float* mw2  = (const float*)d_in[21];
    const float* mb2  = (const float*)d_in[22];
    const float* ew   = (const float*)d_in[23];
    const float* eb   = (const float*)d_in[24];
    const float* elw  = (const float*)d_in[25];
    const float* fw1  = (const float*)d_in[26];
    const float* fb1  = (const float*)d_in[27];
    const float* fw2  = (const float*)d_in[28];
    const float* fb2  = (const float*)d_in[29];

    float* out = (float*)d_out;
    float* out_mech = out + NXD;
    float* out_w    = out + NXD + BS;

    float* fb = nullptr;
    cudaGetSymbolAddress((void**)&fb, g_buf);
    float* gx    = fb + OFF_X;
    float* gpep  = fb + OFF_PEP;
    float* gmech = fb + OFF_MECH;
    float* gb5   = fb + OFF_B5;
    float* gwsm  = fb + OFF_WSM;
    float* gbqkv = fb + OFF_BQKV;

    __half *h16, *qkv16, *ctx16, *ffh16, *pe16, *w16;
    cudaGetSymbolAddress((void**)&h16,   g_h16);
    cudaGetSymbolAddress((void**)&qkv16, g_qkv16);
    cudaGetSymbolAddress((void**)&ctx16, g_ctx16);
    cudaGetSymbolAddress((void**)&ffh16, g_ffh16);
    cudaGetSymbolAddress((void**)&pe16,  g_pe16);
    cudaGetSymbolAddress((void**)&w16,   g_w16);

    // weight conversions (fp32 -> fp16)
    cvt8_k<<<(Dc * Dc / 8 + 255) / 256, 256>>>((const float4*)wi,  (uint4*)(w16 + W16_WI),  Dc * Dc / 8);
    cvt8_k<<<(Dc * Dc / 8 + 255) / 256, 256>>>((const float4*)ow,  (uint4*)(w16 + W16_OW),  Dc * Dc / 8);
    cvt8_k<<<(Dc * DFFc / 8 + 255) / 256, 256>>>((const float4*)fw1, (uint4*)(w16 + W16_FW1), Dc * DFFc / 8);
    cvt8_k<<<(DFFc * Dc / 8 + 255) / 256, 256>>>((const float4*)fw2, (uint4*)(w16 + W16_FW2), DFFc * Dc / 8);
    pack_qkvm_k<<<(Dc * 448) / 256, 256>>>(qw, kw, vw, mw1, qb, kb, vb, mb1,
                                           w16 + W16_QKV, gbqkv);

    // 1) positional/timing embedding
    build_pe_k<<<(Sc * Dc / 4) / 256, 256>>>(pos, tim, pe16);
    hgemm_k<<<dim3(Dc / 128, Sc / 128), 256>>>(pe16, w16 + W16_WI, bi, nullptr, gpep,
                                               Sc, Dc, Dc, 0, 0);
    // 2) x = x_in + pep; norm1 -> h16  (fused)
    ln_addpe_k<<<BS, 256>>>(x_in, gpep, g1, be1, gx, h16);

    // 3) fused QKV + mech-hidden projection (fp16 out)
    hgemm_k<<<dim3(NQKV / 128, BS / 128), 256>>>(h16, w16 + W16_QKV, gbqkv, nullptr, qkv16,
                                                 BS, NQKV, Dc, 2, 1);

    // 4) mechanism output
    mech_out_k<<<BS / 8, 256>>>(qkv16, mw2, mb2, gmech, out_mech);

    // 5) fp16 flash attention -> ctx16
    attn_h_k<<<dim3(Sc / 128, Bc * Hc), 256>>>(qkv16, gmech, ctx16);

    // 6) output projection + residual
    hgemm_k<<<dim3(Dc / 128, BS / 128), 256>>>(ctx16, w16 + W16_OW, ob, gx, gx,
                                               BS, Dc, Dc, 0, 0);

    // 7) five elements (folded to one GEMM)
    layernorm_k<<<BS, 256>>>(gx, g2, be2, h16);
    softmax5_k<<<1, 32>>>(elw, gwsm, out_w);
    combine_w5_k<<<(Dc * Dc / 4) / 256, 256>>>(ew, gwsm, w16 + W16_W5);
    combine_b5_k<<<Dc / 256, 256>>>(eb, gwsm, gb5);
    hgemm_k<<<dim3(Dc / 128, BS / 128), 256>>>(h16, w16 + W16_W5, gb5, gx, gx,
                                               BS, Dc, Dc, 0, 0);

    // 8) FFN
    layernorm_k<<<BS, 256>>>(gx, g3, be3, h16);
    hgemm_k<<<dim3(DFFc / 128, BS / 128), 256>>>(h16, w16 + W16_FW1, fb1, nullptr, ffh16,
                                                 BS, DFFc, Dc, 1, 1);
    hgemm_k<<<dim3(Dc / 128, BS / 128), 256>>>(ffh16, w16 + W16_FW2, fb2, gx, out,
                                               BS, Dc, DFFc, 0, 0);
}